// round 14
// baseline (speedup 1.0000x reference)
#include <cuda_runtime.h>
#include <cuda_bf16.h>
#include <math.h>

#define NB 64
#define NT 512
#define NVARS 16
#define VDIM 16
#define DD 64
#define NTOK (NB*NT)
#define TPB 128
#define MTILE 64
#define LN_EPS 1e-3f

typedef unsigned long long u64;
typedef unsigned int u32;

// prepped weights: per var 9 tiles x 8192B (swizzled [n][k] bf16, 128B rows)
#define WPV_BYTES 73728
__device__ __align__(16) char g_wprep[NVARS * WPV_BYTES];

// tile byte offsets within a var block
#define WT_OFF 0
#define WP_HI 8192
#define WP_LO 16384
#define W1_HI 24576
#define W1_LO 32768
#define W2_HI 40960
#define W2_LO 49152
#define WG_HI 57344
#define WG_LO 65536
// smem byte offsets (single weight buffer; 2 CTAs/SM)
#define WBUF     0           // 73728
#define BIAS_ALL 73728       // 16 x 7 x 64 floats = 28672
#define CPROJ_O  102400      // 16 x 64 floats = 4096
#define WSEL_O   106496      // 64 x 16 floats = 4096
#define CTX_O    110592      // 64 floats
#define SMEM_TOTAL 110848

// ---------------- ptx helpers ----------------
__device__ __forceinline__ u32 smem_u32(const void* p) {
    u32 a;
    asm("{ .reg .u64 t; cvta.to.shared.u64 t, %1; cvt.u32.u64 %0, t; }"
        : "=r"(a) : "l"(p));
    return a;
}

#define LDMX4(r0, r1, r2, r3, addr) \
    asm volatile("ldmatrix.sync.aligned.m8n8.x4.shared.b16 {%0,%1,%2,%3}, [%4];" \
                 : "=r"(r0), "=r"(r1), "=r"(r2), "=r"(r3) : "r"(addr))

#define CP_ASYNC16(dst, src) \
    asm volatile("cp.async.cg.shared.global [%0], [%1], 16;" :: "r"(dst), "l"(src))
#define CP_COMMIT() asm volatile("cp.async.commit_group;")
#define CP_WAIT0() asm volatile("cp.async.wait_group 0;")

__device__ __forceinline__ void mma16816(float* d, u32 a0, u32 a1, u32 a2, u32 a3,
                                         u32 b0, u32 b1) {
    asm volatile(
        "mma.sync.aligned.m16n8k16.row.col.f32.bf16.bf16.f32 "
        "{%0,%1,%2,%3},{%4,%5,%6,%7},{%8,%9},{%0,%1,%2,%3};"
        : "+f"(d[0]), "+f"(d[1]), "+f"(d[2]), "+f"(d[3])
        : "r"(a0), "r"(a1), "r"(a2), "r"(a3), "r"(b0), "r"(b1));
}

__device__ __forceinline__ u32 pkpair(float e0, float e1) {
    u32 r;
    asm("cvt.rn.bf16x2.f32 %0, %1, %2;" : "=r"(r) : "f"(e1), "f"(e0));
    return r;
}
__device__ __forceinline__ u32 pklo(u32 h, float e0, float e1) {
    float h0 = __uint_as_float(h << 16);
    float h1 = __uint_as_float(h & 0xffff0000u);
    return pkpair(e0 - h0, e1 - h1);
}
__device__ __forceinline__ float flo(u32 r) { return __uint_as_float(r << 16); }
__device__ __forceinline__ float fhi(u32 r) { return __uint_as_float(r & 0xffff0000u); }

__device__ __forceinline__ float sigm(float x) {
    return __fdividef(1.f, 1.f + __expf(-x));
}

__device__ __forceinline__ void d_to_frag(const float* D, u32* fh, u32* fl) {
#pragma unroll
    for (int kt = 0; kt < 4; kt++) {
        const float* d0 = D + (2 * kt) * 4;
        const float* d1 = D + (2 * kt + 1) * 4;
        u32 h;
        h = pkpair(d0[0], d0[1]); fh[4*kt+0] = h; fl[4*kt+0] = pklo(h, d0[0], d0[1]);
        h = pkpair(d0[2], d0[3]); fh[4*kt+1] = h; fl[4*kt+1] = pklo(h, d0[2], d0[3]);
        h = pkpair(d1[0], d1[1]); fh[4*kt+2] = h; fl[4*kt+2] = pklo(h, d1[0], d1[1]);
        h = pkpair(d1[2], d1[3]); fh[4*kt+3] = h; fl[4*kt+3] = pklo(h, d1[2], d1[3]);
    }
}

__device__ __forceinline__ void d_init(float* D, const float* bvec, int tig) {
#pragma unroll
    for (int j = 0; j < 8; j++) {
        float2 bv = *(const float2*)(bvec + 8 * j + 2 * tig);
        D[4*j+0] = bv.x; D[4*j+1] = bv.y; D[4*j+2] = bv.x; D[4*j+3] = bv.y;
    }
}

// single layer: D += (Ahi+Alo)@(Whi+Wlo)^T
__device__ __forceinline__ void do_layer(u32 base_hi, u32 base_lo,
                                         const u32* fh, const u32* fl,
                                         float* D, int rowin, int m) {
    const u32 sw = (u32)(rowin << 4);
    const u32 rb = (u32)((m >> 1) * 1024 + rowin * 128);
#pragma unroll
    for (int kt = 0; kt < 4; kt++) {
        u32 csw = ((u32)(32 * kt + 16 * (m & 1))) ^ sw;
        const u32* ah = fh + 4 * kt;
        const u32* al = fl + 4 * kt;
#pragma unroll
        for (int p = 0; p < 4; p++) {
            u32 off = rb + (u32)(p * 2048) + csw;
            u32 bh0, bh1, bh2, bh3, bl0, bl1, bl2, bl3;
            LDMX4(bh0, bh1, bh2, bh3, base_hi + off);
            LDMX4(bl0, bl1, bl2, bl3, base_lo + off);
            mma16816(D + 8*p,     ah[0], ah[1], ah[2], ah[3], bh0, bh1);
            mma16816(D + 8*p + 4, ah[0], ah[1], ah[2], ah[3], bh2, bh3);
            mma16816(D + 8*p,     ah[0], ah[1], ah[2], ah[3], bl0, bl1);
            mma16816(D + 8*p + 4, ah[0], ah[1], ah[2], ah[3], bl2, bl3);
            mma16816(D + 8*p,     al[0], al[1], al[2], al[3], bh0, bh1);
            mma16816(D + 8*p + 4, al[0], al[1], al[2], al[3], bh2, bh3);
        }
    }
}

// fused dual layer: Dr += A@Wp^T, D += A@W1^T interleaved
__device__ __forceinline__ void do_layer2(u32 wph, u32 wpl, u32 w1h, u32 w1l,
                                          const u32* fh, const u32* fl,
                                          float* Dr, float* D, int rowin, int m) {
    const u32 sw = (u32)(rowin << 4);
    const u32 rb = (u32)((m >> 1) * 1024 + rowin * 128);
#pragma unroll
    for (int kt = 0; kt < 4; kt++) {
        u32 csw = ((u32)(32 * kt + 16 * (m & 1))) ^ sw;
        const u32* ah = fh + 4 * kt;
        const u32* al = fl + 4 * kt;
#pragma unroll
        for (int p = 0; p < 4; p++) {
            u32 off = rb + (u32)(p * 2048) + csw;
            u32 ph0, ph1, ph2, ph3, pl0, pl1, pl2, pl3;
            u32 oh0, oh1, oh2, oh3, ol0, ol1, ol2, ol3;
            LDMX4(ph0, ph1, ph2, ph3, wph + off);
            LDMX4(oh0, oh1, oh2, oh3, w1h + off);
            LDMX4(pl0, pl1, pl2, pl3, wpl + off);
            LDMX4(ol0, ol1, ol2, ol3, w1l + off);
            mma16816(Dr + 8*p,     ah[0], ah[1], ah[2], ah[3], ph0, ph1);
            mma16816(D  + 8*p,     ah[0], ah[1], ah[2], ah[3], oh0, oh1);
            mma16816(Dr + 8*p + 4, ah[0], ah[1], ah[2], ah[3], ph2, ph3);
            mma16816(D  + 8*p + 4, ah[0], ah[1], ah[2], ah[3], oh2, oh3);
            mma16816(Dr + 8*p,     ah[0], ah[1], ah[2], ah[3], pl0, pl1);
            mma16816(D  + 8*p,     ah[0], ah[1], ah[2], ah[3], ol0, ol1);
            mma16816(Dr + 8*p + 4, ah[0], ah[1], ah[2], ah[3], pl2, pl3);
            mma16816(D  + 8*p + 4, ah[0], ah[1], ah[2], ah[3], ol2, ol3);
            mma16816(Dr + 8*p,     al[0], al[1], al[2], al[3], ph0, ph1);
            mma16816(D  + 8*p,     al[0], al[1], al[2], al[3], oh0, oh1);
            mma16816(Dr + 8*p + 4, al[0], al[1], al[2], al[3], ph2, ph3);
            mma16816(D  + 8*p + 4, al[0], al[1], al[2], al[3], oh2, oh3);
        }
    }
}

__device__ __forceinline__ void stage_var(u32 dst, const char* src, int tid) {
#pragma unroll
    for (int i = 0; i < 36; i++) {
        int idx = (tid + i * TPB) * 16;
        CP_ASYNC16(dst + (u32)idx, src + idx);
    }
}

// ---------------------------------------------------------------------------
// prep: transpose + hi/lo split; grid (NVARS, 5)
// ---------------------------------------------------------------------------
__global__ void prep_weights_kernel(const float* __restrict__ Wt,
                                    const float* __restrict__ Wp,
                                    const float* __restrict__ W1,
                                    const float* __restrict__ W2,
                                    const float* __restrict__ Wg) {
    int n = blockIdx.x, m = blockIdx.y;
    char* dst = g_wprep + (size_t)n * WPV_BYTES;
    if (m == 0) {
        for (int e = threadIdx.x; e < VDIM * DD; e += blockDim.x) {
            int d = e & 63, v = e >> 6;
            float w = Wt[(size_t)n * VDIM * DD + v * DD + d];
            __nv_bfloat16 hb = __float2bfloat16(w);
            __nv_bfloat16 lb = __float2bfloat16(w - __bfloat162float(hb));
            u32 cs = (u32)(16 * (v >> 3));
            u32 swx = ((u32)(d & 7)) << 4;
            u32 base = (u32)(d * 128) + (u32)((v & 7) * 2);
            *(__nv_bfloat16*)(dst + WT_OFF + base + (cs ^ swx)) = hb;
            *(__nv_bfloat16*)(dst + WT_OFF + base + ((cs + 32) ^ swx)) = lb;
        }
    } else {
        const float* srcs[4] = {Wp + (size_t)n * DD * DD, W1 + (size_t)n * DD * DD,
                                W2 + (size_t)n * DD * DD, Wg + (size_t)n * DD * DD};
        const int hioff[4] = {WP_HI, W1_HI, W2_HI, WG_HI};
        int mm = m - 1;
        const float* s = srcs[mm];
        char* th = dst + hioff[mm];
        char* tl = th + 8192;
        for (int e = threadIdx.x; e < DD * DD; e += blockDim.x) {
            int d = e & 63, k = e >> 6;
            float w = s[k * DD + d];
            __nv_bfloat16 hb = __float2bfloat16(w);
            __nv_bfloat16 lb = __float2bfloat16(w - __bfloat162float(hb));
            u32 cs = (u32)(16 * (k >> 3));
            u32 swx = ((u32)(d & 7)) << 4;
            u32 addr = (u32)(d * 128) + (cs ^ swx) + (u32)((k & 7) * 2);
            *(__nv_bfloat16*)(th + addr) = hb;
            *(__nv_bfloat16*)(tl + addr) = lb;
        }
    }
}

// ---------------------------------------------------------------------------
// main: 64-token tile per CTA (4 warps), 2 CTAs/SM for latency hiding
// ---------------------------------------------------------------------------
__global__ __launch_bounds__(TPB, 2) void vsn_mma_kernel(
    const float* __restrict__ inputs, const float* __restrict__ context,
    const float* __restrict__ Wctx, const float* __restrict__ Wp_g,
    const float* __restrict__ bt, const float* __restrict__ b1,
    const float* __restrict__ b2, const float* __restrict__ bg,
    const float* __restrict__ bp,
    const float* __restrict__ gamma_, const float* __restrict__ beta_,
    const float* __restrict__ Ws, const float* __restrict__ bs,
    float* __restrict__ wout, float* __restrict__ selected) {
    extern __shared__ __align__(128) char sm[];
    const int tid = threadIdx.x;
    const int wid = tid >> 5, lane = tid & 31;
    const int gid = lane >> 2, tig = lane & 3;
    const int rowin = lane & 7, mq = lane >> 3;
    const int row0 = wid * 16 + gid, row1 = row0 + 8;
    const int base = blockIdx.x * MTILE;
    const int bb = base / NT;
    const int tok0 = base + row0, tok1 = base + row1;

    const u32 smb = smem_u32(sm);
    float* bias_all = (float*)(sm + BIAS_ALL);
    float* cproj_s = (float*)(sm + CPROJ_O);
    float* wsel_s  = (float*)(sm + WSEL_O);
    float* ctx_s   = (float*)(sm + CTX_O);

    // phase 0: stage Ws (into WBUF, consumed before var-0 weights land),
    // ctx, biases
    {
        const float4* s = (const float4*)Ws;
        float4* d = (float4*)(sm + WBUF);
        for (int i = tid; i < 1024; i += TPB) d[i] = s[i];
        if (tid < DD) ctx_s[tid] = context[(size_t)bb * DD + tid];
        const float* bsrc[7] = {bt, b1, b2, bg, bp, gamma_, beta_};
        for (int i = tid; i < NVARS * 7 * DD; i += TPB) {
            int n = i / 448, r = i - n * 448, s7 = r >> 6, d7 = r & 63;
            bias_all[i] = bsrc[s7][n * DD + d7];
        }
    }
    __syncthreads();

    // phase 1: softmax (tid<64) | cproj (tid 64..127)
    if (tid < 64) {
        int token = base + tid;
        const float4* xp = (const float4*)(inputs + (size_t)token * 256);
        const float* ws_s = (const float*)(sm + WBUF);
        float l[16];
#pragma unroll
        for (int i = 0; i < 16; i++) l[i] = bs[i];
#pragma unroll 4
        for (int f4 = 0; f4 < 64; ++f4) {
            float4 xv = xp[f4];
            const float* wr = ws_s + f4 * 64;
#pragma unroll
            for (int c = 0; c < 4; c++) {
                float x = (c == 0) ? xv.x : (c == 1) ? xv.y : (c == 2) ? xv.z : xv.w;
                const float* w = wr + c * 16;
#pragma unroll
                for (int i = 0; i < 16; i++) l[i] = fmaf(x, w[i], l[i]);
            }
        }
        float mx = l[0];
#pragma unroll
        for (int i = 1; i < 16; i++) mx = fmaxf(mx, l[i]);
        float s = 0.f;
#pragma unroll
        for (int i = 0; i < 16; i++) { l[i] = __expf(l[i] - mx); s += l[i]; }
        float inv = __fdividef(1.f, s);
        float4* gp = (float4*)(wout + (size_t)token * 16);
        float4* sp = (float4*)(wsel_s + tid * 16);
#pragma unroll
        for (int j = 0; j < 4; j++) {
            float4 o = make_float4(l[4*j] * inv, l[4*j+1] * inv,
                                   l[4*j+2] * inv, l[4*j+3] * inv);
            gp[j] = o;
            sp[j] = o;
        }
    } else {
        // cproj: 64 threads x 16 outputs (n = idx/4, e0 = (idx%4)*16)
        int idx = tid - 64;
        int n = idx >> 2, e0 = (idx & 3) * 16;
        const float* W = Wctx + (size_t)n * DD * DD + e0;
        float acc[16];
#pragma unroll
        for (int i = 0; i < 16; i++) acc[i] = 0.f;
#pragma unroll 4
        for (int d = 0; d < DD; ++d) {
            float c = ctx_s[d];
#pragma unroll
            for (int q = 0; q < 4; q++) {
                float4 w = *(const float4*)(W + d * DD + 4 * q);
                acc[4*q+0] = fmaf(c, w.x, acc[4*q+0]);
                acc[4*q+1] = fmaf(c, w.y, acc[4*q+1]);
                acc[4*q+2] = fmaf(c, w.z, acc[4*q+2]);
                acc[4*q+3] = fmaf(c, w.w, acc[4*q+3]);
            }
        }
        float4* cp = (float4*)(cproj_s + n * DD + e0);
#pragma unroll
        for (int q = 0; q < 4; q++)
            cp[q] = make_float4(acc[4*q+0], acc[4*q+1], acc[4*q+2], acc[4*q+3]);
    }
    __syncthreads();

    // phase 2: kick off var-0 weight staging (overwrites Ws; softmax done),
    // then fold bp' = bp - cproj @ Wp while it streams
    stage_var(smb + WBUF, g_wprep, tid);
    CP_COMMIT();
    {
        int i0 = tid * 8;
        int n = i0 >> 6, e = i0 & 63;
        const float* W = Wp_g + (size_t)n * DD * DD + e;
        const float* cp = cproj_s + n * DD;
        float a[8];
#pragma unroll
        for (int i = 0; i < 8; i++) a[i] = 0.f;
#pragma unroll 8
        for (int d = 0; d < DD; d++) {
            float c = cp[d];
            float4 w0 = *(const float4*)(W + d * DD);
            float4 w1 = *(const float4*)(W + d * DD + 4);
            a[0] = fmaf(c, w0.x, a[0]); a[1] = fmaf(c, w0.y, a[1]);
            a[2] = fmaf(c, w0.z, a[2]); a[3] = fmaf(c, w0.w, a[3]);
            a[4] = fmaf(c, w1.x, a[4]); a[5] = fmaf(c, w1.y, a[5]);
            a[6] = fmaf(c, w1.z, a[6]); a[7] = fmaf(c, w1.w, a[7]);
        }
        float* dstp = bias_all + n * 448 + 4 * DD + e;
#pragma unroll
        for (int i = 0; i < 8; i++) dstp[i] -= a[i];
    }

    float sel[32];
#pragma unroll
    for (int i = 0; i < 32; i++) sel[i] = 0.f;

    const u32 wb = smb + WBUF;

    for (int n = 0; n < NVARS; ++n) {
        if (n > 0) {
            stage_var(wb, g_wprep + (size_t)n * WPV_BYTES, tid);
            CP_COMMIT();
        }
        CP_WAIT0();
        __syncthreads();   // weights (and phase-2 bias writes at n=0) visible

        const float* bv = bias_all + n * 448;

        // ---- layer 1: t = x @ Wt + bt (k=16) ----
        float D[32];
        d_init(D, bv + 0 * DD, tig);
        {
            const float* xb0 = inputs + (size_t)tok0 * 256 + n * VDIM;
            const float* xb1 = inputs + (size_t)tok1 * 256 + n * VDIM;
            float2 x00 = *(const float2*)(xb0 + 2 * tig);
            float2 x10 = *(const float2*)(xb1 + 2 * tig);
            float2 x01 = *(const float2*)(xb0 + 8 + 2 * tig);
            float2 x11 = *(const float2*)(xb1 + 8 + 2 * tig);
            u32 axh[4], axl[4];
            axh[0] = pkpair(x00.x, x00.y); axl[0] = pklo(axh[0], x00.x, x00.y);
            axh[1] = pkpair(x10.x, x10.y); axl[1] = pklo(axh[1], x10.x, x10.y);
            axh[2] = pkpair(x01.x, x01.y); axl[2] = pklo(axh[2], x01.x, x01.y);
            axh[3] = pkpair(x11.x, x11.y); axl[3] = pklo(axh[3], x11.x, x11.y);

            const u32 sw = (u32)(rowin << 4);
            const u32 rb = (u32)((mq >> 1) * 1024 + rowin * 128);
            u32 csh = ((u32)(16 * (mq & 1))) ^ sw;
            u32 csl = ((u32)(32 + 16 * (mq & 1))) ^ sw;
#pragma unroll
            for (int p = 0; p < 4; p++) {
                u32 off = rb + (u32)(p * 2048);
                u32 bh0, bh1, bh2, bh3, bl0, bl1, bl2, bl3;
                LDMX4(bh0, bh1, bh2, bh3, wb + WT_OFF + off + csh);
                LDMX4(bl0, bl1, bl2, bl3, wb + WT_OFF + off + csl);
                mma16816(D + 8*p,     axh[0], axh[1], axh[2], axh[3], bh0, bh1);
                mma16816(D + 8*p + 4, axh[0], axh[1], axh[2], axh[3], bh2, bh3);
                mma16816(D + 8*p,     axh[0], axh[1], axh[2], axh[3], bl0, bl1);
                mma16816(D + 8*p + 4, axh[0], axh[1], axh[2], axh[3], bl2, bl3);
                mma16816(D + 8*p,     axl[0], axl[1], axl[2], axl[3], bh0, bh1);
                mma16816(D + 8*p + 4, axl[0], axl[1], axl[2], axl[3], bh2, bh3);
            }
        }

        // ---- a = t + cproj ; one frag conversion feeds Wp AND W1 ----
#pragma unroll
        for (int j = 0; j < 8; j++) {
            float2 cp = *(const float2*)(cproj_s + n * DD + 8 * j + 2 * tig);
            D[4*j+0] += cp.x; D[4*j+1] += cp.y;
            D[4*j+2] += cp.x; D[4*j+3] += cp.y;
        }
        u32 fh[16], fl[16];
        d_to_frag(D, fh, fl);      // a fragments

        // ---- fused: residual = a@Wp + bp'  ||  h1pre = a@W1 + b1 ----
        float Dres[32];
        d_init(Dres, bv + 4 * DD, tig);
        d_init(D, bv + 1 * DD, tig);
        do_layer2(wb + WP_HI, wb + WP_LO, wb + W1_HI, wb + W1_LO,
                  fh, fl, Dres, D, rowin, mq);

        // ---- h1 = elu(h1pre) ----
#pragma unroll
        for (int i = 0; i < 32; i++) {
            float x = D[i];
            D[i] = x > 0.f ? x : (__expf(x) - 1.f);
        }
        d_to_frag(D, fh, fl);

        // ---- h2 = h1 @ W2 + b2 ----
        d_init(D, bv + 2 * DD, tig);
        do_layer(wb + W2_HI, wb + W2_LO, fh, fl, D, rowin, mq);
        d_to_frag(D, fh, fl);      // h2 fragments

        // ---- gate logits = h2 @ Wg + bg ----
        d_init(D, bv + 3 * DD, tig);
        do_layer(wb + WG_HI, wb + WG_LO, fh, fl, D, rowin, mq);

        // ---- y, LN, weighted select ----
        float sum0 = 0.f, sq0 = 0.f, sum1 = 0.f, sq1 = 0.f;
#pragma unroll
        for (int j = 0; j < 8; j++) {
            int o = 4 * (j >> 1) + 2 * (j & 1);
            u32 h0 = fh[o], l0 = fl[o], h1r = fh[o + 1], l1r = fl[o + 1];
            float h2a = flo(h0) + flo(l0), h2b = fhi(h0) + fhi(l0);
            float h2c = flo(h1r) + flo(l1r), h2d = fhi(h1r) + fhi(l1r);
            float y0 = fmaf(sigm(D[4*j+0]), h2a, Dres[4*j+0]);
            float y1 = fmaf(sigm(D[4*j+1]), h2b, Dres[4*j+1]);
            float y2 = fmaf(sigm(D[4*j+2]), h2c, Dres[4*j+2]);
            float y3 = fmaf(sigm(D[4*j+3]), h2d, Dres[4*j+3]);
            D[4*j+0] = y0; D[4*j+1] = y1; D[4*j+2] = y2; D[4*j+3] = y3;
            sum0 += y0 + y1; sq0 = fmaf(y0, y0, fmaf(y1, y1, sq0));
            sum1 += y2 + y3; sq1 = fmaf(y2, y2, fmaf(y3, y3, sq1));
        }
        sum0 += __shfl_xor_sync(0xffffffffu, sum0, 1);
        sum0 += __shfl_xor_sync(0xffffffffu, sum0, 2);
        sq0  += __shfl_xor_sync(0xffffffffu, sq0, 1);
        sq0  += __shfl_xor_sync(0xffffffffu, sq0, 2);
        sum1 += __shfl_xor_sync(0xffffffffu, sum1, 1);
        sum1 += __shfl_xor_sync(0xffffffffu, sum1, 2);
        sq1  += __shfl_xor_sync(0xffffffffu, sq1, 1);
        sq1  += __shfl_xor_sync(0xffffffffu, sq1, 2);
        float mu0 = sum0 * (1.f / 64.f);
        float rs0 = rsqrtf(sq0 * (1.f / 64.f) - mu0 * mu0 + LN_EPS);
        float mu1 = sum1 * (1.f / 64.f);
        float rs1 = rsqrtf(sq1 * (1.f / 64.f) - mu1 * mu1 + LN_EPS);
        float w0 = wsel_s[row0 * NVARS + n];
        float w1 = wsel_s[row1 * NVARS + n];
#pragma unroll
        for (int j = 0; j < 8; j++) {
            float2 gm = *(const float2*)(bv + 5 * DD + 8 * j + 2 * tig);
            float2 be = *(const float2*)(bv + 6 * DD + 8 * j + 2 * tig);
            float yn0 = fmaf((D[4*j+0] - mu0) * rs0, gm.x, be.x);
            float yn1 = fmaf((D[4*j+1] - mu0) * rs0, gm.y, be.y);
            float yn2 = fmaf((D[4*j+2] - mu1) * rs1, gm.x, be.x);
            float yn3 = fmaf((D[4*j+3] - mu1) * rs1, gm.y, be.y);
            sel[4*j+0] = fmaf(w0, yn0, sel[4*j+0]);
            sel[4*j+1] = fmaf(w0, yn1, sel[4*j+1]);
            sel[4*j+2] = fmaf(w1, yn2, sel[4*j+2]);
            sel[4*j+3] = fmaf(w1, yn3, sel[4*j+3]);
        }
        __syncthreads();   // weight-buffer reads done before next stage
    }

    // ---- output ----
#pragma unroll
    for (int j = 0; j < 8; j++) {
        *(float2*)(selected + (size_t)tok0 * DD + 8 * j + 2 * tig)
            = make_float2(sel[4*j+0], sel[4*j+1]);
        *(float2*)(selected + (size_t)tok1 * DD + 8 * j + 2 * tig)
            = make_float2(sel[4*j+2], sel[4*j+3]);
    }
}

// ---------------------------------------------------------------------------
extern "C" void kernel_launch(void* const* d_in, const int* in_sizes, int n_in,
                              void* d_out, int out_size) {
    const float* inputs  = (const float*)d_in[0];
    const float* context = (const float*)d_in[1];
    const float* Wt   = (const float*)d_in[2];
    const float* bt   = (const float*)d_in[3];
    const float* Wctx = (const float*)d_in[4];
    const float* W1   = (const float*)d_in[5];
    const float* b1   = (const float*)d_in[6];
    const float* W2   = (const float*)d_in[7];
    const float* b2   = (const float*)d_in[8];
    const float* Wg   = (const float*)d_in[9];
    const float* bg   = (const float*)d_in[10];
    const float* Wp   = (const float*)d_in[11];
    const float* bp   = (const float*)d_in[12];
    const float* gam  = (const float*)d_in[13];
    const float* bet  = (const float*)d_in[14];
    const float* Ws   = (const float*)d_in[15];
    const float* bs   = (const float*)d_in[16];

    float* selected = (float*)d_out;
    float* wout = selected + (size_t)NTOK * DD;

    prep_weights_kernel<<<dim3(NVARS, 5), 256>>>(Wt, Wp, W1, W2, Wg);

    cudaFuncSetAttribute(vsn_mma_kernel,
                         cudaFuncAttributeMaxDynamicSharedMemorySize, SMEM_TOTAL);
    vsn_mma_kernel<<<NTOK / MTILE, TPB, SMEM_TOTAL>>>(
        inputs, context, Wctx, Wp, bt, b1, b2, bg, bp, gam, bet, Ws, bs,
        wout, selected);
}

// round 15
// speedup vs baseline: 1.3140x; 1.3140x over previous
#include <cuda_runtime.h>
#include <cuda_fp16.h>
#include <math.h>

#define NB 64
#define NT 512
#define NVARS 16
#define VDIM 16
#define DD 64
#define NTOK (NB*NT)
#define TPB 256
#define MTILE 128
#define LN_EPS 1e-3f

typedef unsigned long long u64;
typedef unsigned int u32;

// prepped weights: per var 5 tiles x 8192B (swizzled [n][k] fp16, 128B rows)
#define WPV_BYTES 40960
__device__ __align__(16) char g_wprep[NVARS * WPV_BYTES];

// tile byte offsets within a var block
#define WT_OFF 0
#define WP_OFF 8192
#define W1_OFF 16384
#define W2_OFF 24576
#define WG_OFF 32768
// smem byte offsets
#define WBUF0    0           // 40960
#define WBUF1    40960
#define BIAS_ALL 81920       // 16 x 7 x 64 floats = 28672
#define CPROJ_O  110592      // 16 x 64 floats = 4096
#define WSEL_O   114688      // 128 x 16 floats = 8192
#define CTX_O    122880      // 64 floats
#define SMEM_TOTAL 123136

// ---------------- ptx helpers ----------------
__device__ __forceinline__ u32 smem_u32(const void* p) {
    u32 a;
    asm("{ .reg .u64 t; cvta.to.shared.u64 t, %1; cvt.u32.u64 %0, t; }"
        : "=r"(a) : "l"(p));
    return a;
}

#define LDMX4(r0, r1, r2, r3, addr) \
    asm volatile("ldmatrix.sync.aligned.m8n8.x4.shared.b16 {%0,%1,%2,%3}, [%4];" \
                 : "=r"(r0), "=r"(r1), "=r"(r2), "=r"(r3) : "r"(addr))

#define CP_ASYNC16(dst, src) \
    asm volatile("cp.async.cg.shared.global [%0], [%1], 16;" :: "r"(dst), "l"(src))
#define CP_COMMIT() asm volatile("cp.async.commit_group;")
#define CP_WAIT1() asm volatile("cp.async.wait_group 1;")
#define CP_WAIT0() asm volatile("cp.async.wait_group 0;")

__device__ __forceinline__ void mma16816(float* d, u32 a0, u32 a1, u32 a2, u32 a3,
                                         u32 b0, u32 b1) {
    asm volatile(
        "mma.sync.aligned.m16n8k16.row.col.f32.f16.f16.f32 "
        "{%0,%1,%2,%3},{%4,%5,%6,%7},{%8,%9},{%0,%1,%2,%3};"
        : "+f"(d[0]), "+f"(d[1]), "+f"(d[2]), "+f"(d[3])
        : "r"(a0), "r"(a1), "r"(a2), "r"(a3), "r"(b0), "r"(b1));
}

// pack (e0, e1) -> f16x2 with e0 in LOW half
__device__ __forceinline__ u32 pkpair(float e0, float e1) {
    u32 r;
    asm("cvt.rn.f16x2.f32 %0, %1, %2;" : "=r"(r) : "f"(e1), "f"(e0));
    return r;
}
__device__ __forceinline__ float flo(u32 r) {
    __half2 h = *reinterpret_cast<__half2*>(&r);
    return __low2float(h);
}
__device__ __forceinline__ float fhi(u32 r) {
    __half2 h = *reinterpret_cast<__half2*>(&r);
    return __high2float(h);
}
__device__ __forceinline__ u32 pklo(u32 h, float e0, float e1) {
    return pkpair(e0 - flo(h), e1 - fhi(h));
}

__device__ __forceinline__ float sigm(float x) {
    return __fdividef(1.f, 1.f + __expf(-x));
}

__device__ __forceinline__ void d_to_frag(const float* D, u32* fh, u32* fl) {
#pragma unroll
    for (int kt = 0; kt < 4; kt++) {
        const float* d0 = D + (2 * kt) * 4;
        const float* d1 = D + (2 * kt + 1) * 4;
        u32 h;
        h = pkpair(d0[0], d0[1]); fh[4*kt+0] = h; fl[4*kt+0] = pklo(h, d0[0], d0[1]);
        h = pkpair(d0[2], d0[3]); fh[4*kt+1] = h; fl[4*kt+1] = pklo(h, d0[2], d0[3]);
        h = pkpair(d1[0], d1[1]); fh[4*kt+2] = h; fl[4*kt+2] = pklo(h, d1[0], d1[1]);
        h = pkpair(d1[2], d1[3]); fh[4*kt+3] = h; fl[4*kt+3] = pklo(h, d1[2], d1[3]);
    }
}

__device__ __forceinline__ void d_init(float* D, const float* bvec, int tig) {
#pragma unroll
    for (int j = 0; j < 8; j++) {
        float2 bv = *(const float2*)(bvec + 8 * j + 2 * tig);
        D[4*j+0] = bv.x; D[4*j+1] = bv.y; D[4*j+2] = bv.x; D[4*j+3] = bv.y;
    }
}

// single layer, single-fp16 B: D += (Ahi+Alo)@B^T   (4 MMAs per kt,p)
__device__ __forceinline__ void do_layer(u32 base,
                                         const u32* fh, const u32* fl,
                                         float* D, int rowin, int m) {
    const u32 sw = (u32)(rowin << 4);
    const u32 rb = (u32)((m >> 1) * 1024 + rowin * 128);
#pragma unroll
    for (int kt = 0; kt < 4; kt++) {
        u32 csw = ((u32)(32 * kt + 16 * (m & 1))) ^ sw;
        const u32* ah = fh + 4 * kt;
        const u32* al = fl + 4 * kt;
#pragma unroll
        for (int p = 0; p < 4; p++) {
            u32 off = rb + (u32)(p * 2048) + csw;
            u32 b0, b1, b2, b3;
            LDMX4(b0, b1, b2, b3, base + off);
            mma16816(D + 8*p,     ah[0], ah[1], ah[2], ah[3], b0, b1);
            mma16816(D + 8*p + 4, ah[0], ah[1], ah[2], ah[3], b2, b3);
            mma16816(D + 8*p,     al[0], al[1], al[2], al[3], b0, b1);
            mma16816(D + 8*p + 4, al[0], al[1], al[2], al[3], b2, b3);
        }
    }
}

// fused dual layer: Dr += A@Wp^T, D += A@W1^T, MMAs alternating chains
__device__ __forceinline__ void do_layer2(u32 wp, u32 w1,
                                          const u32* fh, const u32* fl,
                                          float* Dr, float* D, int rowin, int m) {
    const u32 sw = (u32)(rowin << 4);
    const u32 rb = (u32)((m >> 1) * 1024 + rowin * 128);
#pragma unroll
    for (int kt = 0; kt < 4; kt++) {
        u32 csw = ((u32)(32 * kt + 16 * (m & 1))) ^ sw;
        const u32* ah = fh + 4 * kt;
        const u32* al = fl + 4 * kt;
#pragma unroll
        for (int p = 0; p < 4; p++) {
            u32 off = rb + (u32)(p * 2048) + csw;
            u32 p0, p1, p2, p3, o0, o1, o2, o3;
            LDMX4(p0, p1, p2, p3, wp + off);
            LDMX4(o0, o1, o2, o3, w1 + off);
            mma16816(Dr + 8*p,     ah[0], ah[1], ah[2], ah[3], p0, p1);
            mma16816(D  + 8*p,     ah[0], ah[1], ah[2], ah[3], o0, o1);
            mma16816(Dr + 8*p + 4, ah[0], ah[1], ah[2], ah[3], p2, p3);
            mma16816(D  + 8*p + 4, ah[0], ah[1], ah[2], ah[3], o2, o3);
            mma16816(Dr + 8*p,     al[0], al[1], al[2], al[3], p0, p1);
            mma16816(D  + 8*p,     al[0], al[1], al[2], al[3], o0, o1);
            mma16816(Dr + 8*p + 4, al[0], al[1], al[2], al[3], p2, p3);
            mma16816(D  + 8*p + 4, al[0], al[1], al[2], al[3], o2, o3);
        }
    }
}

__device__ __forceinline__ void prefetch_var(u32 dst, const char* src, int tid) {
#pragma unroll
    for (int i = 0; i < 10; i++) {
        int idx = (tid + i * 256) * 16;
        CP_ASYNC16(dst + (u32)idx, src + idx);
    }
}

// ---------------------------------------------------------------------------
// prep: transpose + fp16 convert into swizzled [n][k] tiles; grid (NVARS, 5)
// ---------------------------------------------------------------------------
__global__ void prep_weights_kernel(const float* __restrict__ Wt,
                                    const float* __restrict__ Wp,
                                    const float* __restrict__ W1,
                                    const float* __restrict__ W2,
                                    const float* __restrict__ Wg) {
    int n = blockIdx.x, m = blockIdx.y;
    char* dst = g_wprep + (size_t)n * WPV_BYTES;
    if (m == 0) {
        for (int e = threadIdx.x; e < VDIM * DD; e += blockDim.x) {
            int d = e & 63, v = e >> 6;
            float w = Wt[(size_t)n * VDIM * DD + v * DD + d];
            u32 cs = (u32)(16 * (v >> 3));
            u32 swx = ((u32)(d & 7)) << 4;
            u32 addr = (u32)(d * 128) + (cs ^ swx) + (u32)((v & 7) * 2);
            *(__half*)(dst + WT_OFF + addr) = __float2half(w);
        }
    } else {
        const float* srcs[4] = {Wp + (size_t)n * DD * DD, W1 + (size_t)n * DD * DD,
                                W2 + (size_t)n * DD * DD, Wg + (size_t)n * DD * DD};
        const int toff[4] = {WP_OFF, W1_OFF, W2_OFF, WG_OFF};
        int mm = m - 1;
        const float* s = srcs[mm];
        char* th = dst + toff[mm];
        for (int e = threadIdx.x; e < DD * DD; e += blockDim.x) {
            int d = e & 63, k = e >> 6;
            float w = s[k * DD + d];
            u32 cs = (u32)(16 * (k >> 3));
            u32 swx = ((u32)(d & 7)) << 4;
            u32 addr = (u32)(d * 128) + (cs ^ swx) + (u32)((k & 7) * 2);
            *(__half*)(th + addr) = __float2half(w);
        }
    }
}

// ---------------------------------------------------------------------------
// main
// ---------------------------------------------------------------------------
__global__ __launch_bounds__(TPB, 1) void vsn_mma_kernel(
    const float* __restrict__ inputs, const float* __restrict__ context,
    const float* __restrict__ Wctx, const float* __restrict__ Wp_g,
    const float* __restrict__ bt, const float* __restrict__ b1,
    const float* __restrict__ b2, const float* __restrict__ bg,
    const float* __restrict__ bp,
    const float* __restrict__ gamma_, const float* __restrict__ beta_,
    const float* __restrict__ Ws, const float* __restrict__ bs,
    float* __restrict__ wout, float* __restrict__ selected) {
    extern __shared__ __align__(128) char sm[];
    const int tid = threadIdx.x;
    const int wid = tid >> 5, lane = tid & 31;
    const int gid = lane >> 2, tig = lane & 3;
    const int rowin = lane & 7, mq = lane >> 3;
    const int row0 = wid * 16 + gid, row1 = row0 + 8;
    const int base = blockIdx.x * MTILE;
    const int bb = base / NT;
    const int tok0 = base + row0, tok1 = base + row1;

    const u32 smb = smem_u32(sm);
    float* bias_all = (float*)(sm + BIAS_ALL);
    float* cproj_s = (float*)(sm + CPROJ_O);
    float* wsel_s  = (float*)(sm + WSEL_O);
    float* ctx_s   = (float*)(sm + CTX_O);

    // prefetch var 0 weights
    prefetch_var(smb + WBUF0, g_wprep, tid);
    CP_COMMIT();

    // stage Ws (WBUF1, free until var-1 prefetch), ctx, biases
    {
        const float4* s = (const float4*)Ws;
        float4* d = (float4*)(sm + WBUF1);
        for (int i = tid; i < 1024; i += TPB) d[i] = s[i];
        if (tid < DD) ctx_s[tid] = context[(size_t)bb * DD + tid];
        const float* bsrc[7] = {bt, b1, b2, bg, bp, gamma_, beta_};
        for (int i = tid; i < NVARS * 7 * DD; i += TPB) {
            int n = i / 448, r = i - n * 448, s7 = r >> 6, d7 = r & 63;
            bias_all[i] = bsrc[s7][n * DD + d7];
        }
    }
    __syncthreads();

    if (tid < 128) {
        // softmax for token base+tid
        int token = base + tid;
        const float4* xp = (const float4*)(inputs + (size_t)token * 256);
        const float* ws_s = (const float*)(sm + WBUF1);
        float l[16];
#pragma unroll
        for (int i = 0; i < 16; i++) l[i] = bs[i];
#pragma unroll 4
        for (int f4 = 0; f4 < 64; ++f4) {
            float4 xv = xp[f4];
            const float* wr = ws_s + f4 * 64;
#pragma unroll
            for (int c = 0; c < 4; c++) {
                float x = (c == 0) ? xv.x : (c == 1) ? xv.y : (c == 2) ? xv.z : xv.w;
                const float* w = wr + c * 16;
#pragma unroll
                for (int i = 0; i < 16; i++) l[i] = fmaf(x, w[i], l[i]);
            }
        }
        float mx = l[0];
#pragma unroll
        for (int i = 1; i < 16; i++) mx = fmaxf(mx, l[i]);
        float s = 0.f;
#pragma unroll
        for (int i = 0; i < 16; i++) { l[i] = __expf(l[i] - mx); s += l[i]; }
        float inv = __fdividef(1.f, s);
        float4* gp = (float4*)(wout + (size_t)token * 16);
        float4* sp = (float4*)(wsel_s + tid * 16);
#pragma unroll
        for (int j = 0; j < 4; j++) {
            float4 o = make_float4(l[4*j] * inv, l[4*j+1] * inv,
                                   l[4*j+2] * inv, l[4*j+3] * inv);
            gp[j] = o;
            sp[j] = o;
        }
    } else {
        // cproj: 128 threads x 8 outputs
        int idx = tid - 128;
        int n = idx >> 3, e0 = (idx & 7) * 8;
        const float* W = Wctx + (size_t)n * DD * DD + e0;
        float acc[8];
#pragma unroll
        for (int i = 0; i < 8; i++) acc[i] = 0.f;
#pragma unroll 8
        for (int d = 0; d < DD; ++d) {
            float c = ctx_s[d];
            float4 w0 = *(const float4*)(W + d * DD);
            float4 w1 = *(const float4*)(W + d * DD + 4);
            acc[0] = fmaf(c, w0.x, acc[0]); acc[1] = fmaf(c, w0.y, acc[1]);
            acc[2] = fmaf(c, w0.z, acc[2]); acc[3] = fmaf(c, w0.w, acc[3]);
            acc[4] = fmaf(c, w1.x, acc[4]); acc[5] = fmaf(c, w1.y, acc[5]);
            acc[6] = fmaf(c, w1.z, acc[6]); acc[7] = fmaf(c, w1.w, acc[7]);
        }
        float4* cp = (float4*)(cproj_s + n * DD + e0);
        cp[0] = make_float4(acc[0], acc[1], acc[2], acc[3]);
        cp[1] = make_float4(acc[4], acc[5], acc[6], acc[7]);
    }
    __syncthreads();

    // phase 2: bp' = bp - cproj @ Wp
    {
        int i0 = tid * 4;
        int n = i0 >> 6, e = i0 & 63;
        const float* W = Wp_g + (size_t)n * DD * DD + e;
        const float* cp = cproj_s + n * DD;
        float a0 = 0.f, a1 = 0.f, a2 = 0.f, a3 = 0.f;
#pragma unroll 8
        for (int d = 0; d < DD; d++) {
            float c = cp[d];
            float4 w = *(const float4*)(W + d * DD);
            a0 = fmaf(c, w.x, a0); a1 = fmaf(c, w.y, a1);
            a2 = fmaf(c, w.z, a2); a3 = fmaf(c, w.w, a3);
        }
        float* dstp = bias_all + n * 448 + 4 * DD + e;
        dstp[0] -= a0; dstp[1] -= a1; dstp[2] -= a2; dstp[3] -= a3;
    }
    __syncthreads();

    float sel[32];
#pragma unroll
    for (int i = 0; i < 32; i++) sel[i] = 0.f;

    for (int n = 0; n < NVARS; ++n) {
        if (n < NVARS - 1) {
            prefetch_var(smb + (((n + 1) & 1) ? WBUF1 : WBUF0),
                         g_wprep + (size_t)(n + 1) * WPV_BYTES, tid);
            CP_COMMIT();
            CP_WAIT1();
        } else {
            CP_WAIT0();
        }
        __syncthreads();

        const u32 wb = smb + ((n & 1) ? WBUF1 : WBUF0);
        const float* bv = bias_all + n * 448;

        // ---- layer 1: t = x @ Wt + bt (k=16) ----
        float D[32];
        d_init(D, bv + 0 * DD, tig);
        {
            const float* xb0 = inputs + (size_t)tok0 * 256 + n * VDIM;
            const float* xb1 = inputs + (size_t)tok1 * 256 + n * VDIM;
            float2 x00 = *(const float2*)(xb0 + 2 * tig);
            float2 x10 = *(const float2*)(xb1 + 2 * tig);
            float2 x01 = *(const float2*)(xb0 + 8 + 2 * tig);
            float2 x11 = *(const float2*)(xb1 + 8 + 2 * tig);
            u32 axh[4], axl[4];
            axh[0] = pkpair(x00.x, x00.y); axl[0] = pklo(axh[0], x00.x, x00.y);
            axh[1] = pkpair(x10.x, x10.y); axl[1] = pklo(axh[1], x10.x, x10.y);
            axh[2] = pkpair(x01.x, x01.y); axl[2] = pklo(axh[2], x01.x, x01.y);
            axh[3] = pkpair(x11.x, x11.y); axl[3] = pklo(axh[3], x11.x, x11.y);

            const u32 sw = (u32)(rowin << 4);
            const u32 rb = (u32)((mq >> 1) * 1024 + rowin * 128);
            u32 csh = ((u32)(16 * (mq & 1))) ^ sw;
#pragma unroll
            for (int p = 0; p < 4; p++) {
                u32 off = rb + (u32)(p * 2048) + csh;
                u32 b0, b1, b2, b3;
                LDMX4(b0, b1, b2, b3, wb + WT_OFF + off);
                mma16816(D + 8*p,     axh[0], axh[1], axh[2], axh[3], b0, b1);
                mma16816(D + 8*p + 4, axh[0], axh[1], axh[2], axh[3], b2, b3);
                mma16816(D + 8*p,     axl[0], axl[1], axl[2], axl[3], b0, b1);
                mma16816(D + 8*p + 4, axl[0], axl[1], axl[2], axl[3], b2, b3);
            }
        }

        // ---- a = t + cproj ; one frag conversion feeds Wp AND W1 ----
#pragma unroll
        for (int j = 0; j < 8; j++) {
            float2 cp = *(const float2*)(cproj_s + n * DD + 8 * j + 2 * tig);
            D[4*j+0] += cp.x; D[4*j+1] += cp.y;
            D[4*j+2] += cp.x; D[4*j+3] += cp.y;
        }
        u32 fh[16], fl[16];
        d_to_frag(D, fh, fl);      // a fragments

        // ---- fused: residual = a@Wp + bp'  ||  h1pre = a@W1 + b1 ----
        float Dres[32];
        d_init(Dres, bv + 4 * DD, tig);
        d_init(D, bv + 1 * DD, tig);
        do_layer2(wb + WP_OFF, wb + W1_OFF, fh, fl, Dres, D, rowin, mq);

        // ---- h1 = elu(h1pre) ----
#pragma unroll
        for (int i = 0; i < 32; i++) {
            float x = D[i];
            D[i] = x > 0.f ? x : (__expf(x) - 1.f);
        }
        d_to_frag(D, fh, fl);

        // ---- h2 = h1 @ W2 + b2 ----
        d_init(D, bv + 2 * DD, tig);
        do_layer(wb + W2_OFF, fh, fl, D, rowin, mq);
        d_to_frag(D, fh, fl);      // h2 fragments

        // ---- gate logits = h2 @ Wg + bg ----
        d_init(D, bv + 3 * DD, tig);
        do_layer(wb + WG_OFF, fh, fl, D, rowin, mq);

        // ---- y, LN, weighted select ----
        float sum0 = 0.f, sq0 = 0.f, sum1 = 0.f, sq1 = 0.f;
#pragma unroll
        for (int j = 0; j < 8; j++) {
            int o = 4 * (j >> 1) + 2 * (j & 1);
            u32 h0 = fh[o], l0 = fl[o], h1r = fh[o + 1], l1r = fl[o + 1];
            float h2a = flo(h0) + flo(l0), h2b = fhi(h0) + fhi(l0);
            float h2c = flo(h1r) + flo(l1r), h2d = fhi(h1r) + fhi(l1r);
            float y0 = fmaf(sigm(D[4*j+0]), h2a, Dres[4*j+0]);
            float y1 = fmaf(sigm(D[4*j+1]), h2b, Dres[4*j+1]);
            float y2 = fmaf(sigm(D[4*j+2]), h2c, Dres[4*j+2]);
            float y3 = fmaf(sigm(D[4*j+3]), h2d, Dres[4*j+3]);
            D[4*j+0] = y0; D[4*j+1] = y1; D[4*j+2] = y2; D[4*j+3] = y3;
            sum0 += y0 + y1; sq0 = fmaf(y0, y0, fmaf(y1, y1, sq0));
            sum1 += y2 + y3; sq1 = fmaf(y2, y2, fmaf(y3, y3, sq1));
        }
        sum0 += __shfl_xor_sync(0xffffffffu, sum0, 1);
        sum0 += __shfl_xor_sync(0xffffffffu, sum0, 2);
        sq0  += __shfl_xor_sync(0xffffffffu, sq0, 1);
        sq0  += __shfl_xor_sync(0xffffffffu, sq0, 2);
        sum1 += __shfl_xor_sync(0xffffffffu, sum1, 1);
        sum1 += __shfl_xor_sync(0xffffffffu, sum1, 2);
        sq1  += __shfl_xor_sync(0xffffffffu, sq1, 1);
        sq1  += __shfl_xor_sync(0xffffffffu, sq1, 2);
        float mu0 = sum0 * (1.f / 64.f);
        float rs0 = rsqrtf(sq0 * (1.f / 64.f) - mu0 * mu0 + LN_EPS);
        float mu1 = sum1 * (1.f / 64.f);
        float rs1 = rsqrtf(sq1 * (1.f / 64.f) - mu1 * mu1 + LN_EPS);
        float w0 = wsel_s[row0 * NVARS + n];
        float w1 = wsel_s[row1 * NVARS + n];
#pragma unroll
        for (int j = 0; j < 8; j++) {
            float2 gm = *(const float2*)(bv + 5 * DD + 8 * j + 2 * tig);
            float2 be = *(const float2*)(bv + 6 * DD + 8 * j + 2 * tig);
            float yn0 = fmaf((D[4*j+0] - mu0) * rs0, gm.x, be.x);
            float yn1 = fmaf((D[4*j+1] - mu0) * rs0, gm.y, be.y);
            float yn2 = fmaf((D[4*j+2] - mu1) * rs1, gm.x, be.x);
            float yn3 = fmaf((D[4*j+3] - mu1) * rs1, gm.y, be.y);
            sel[4*j+0] = fmaf(w0, yn0, sel[4*j+0]);
            sel[4*j+1] = fmaf(w0, yn1, sel[4*j+1]);
            sel[4*j+2] = fmaf(w1, yn2, sel[4*j+2]);
            sel[4*j+3] = fmaf(w1, yn3, sel[4*j+3]);
        }
        __syncthreads();
    }

    // ---- output ----
#pragma unroll
    for (int j = 0; j < 8; j++) {
        *(float2*)(selected + (size_t)tok0 * DD + 8 * j + 2 * tig)
            = make_float2(sel[4*j+0], sel[4*j+1]);
        *(float2*)(selected + (size_t)tok1 * DD + 8 * j + 2 * tig)
            = make_float2(sel[4*j+2], sel[4*j+3]);
    }
}

// ---------------------------------------------------------------------------
extern "C" void kernel_launch(void* const* d_in, const int* in_sizes, int n_in,
                              void* d_out, int out_size) {
    const float* inputs  = (const float*)d_in[0];
    const float* context = (const float*)d_in[1];
    const float* Wt   = (const float*)d_in[2];
    const float* bt   = (const float*)d_in[3];
    const float* Wctx = (const float*)d_in[4];
    const float* W1   = (const float*)d_in[5];
    const float* b1   = (const float*)d_in[6];
    const float* W2   = (const float*)d_in[7];
    const float* b2   = (const float*)d_in[8];
    const float* Wg   = (const float*)d_in[9];
    const float* bg   = (const float*)d_in[10];
    const float* Wp   = (const float*)d_in[11];
    const float* bp   = (const float*)d_in[12];
    const float* gam  = (const float*)d_in[13];
    const float* bet  = (const float*)d_in[14];
    const float* Ws   = (const float*)d_in[15];
    const float* bs   = (const float*)d_in[16];

    float* selected = (float*)d_out;
    float* wout = selected + (size_t)NTOK * DD;

    prep_weights_kernel<<<dim3(NVARS, 5), 256>>>(Wt, Wp, W1, W2, Wg);

    cudaFuncSetAttribute(vsn_mma_kernel,
                         cudaFuncAttributeMaxDynamicSharedMemorySize, SMEM_TOTAL);
    vsn_mma_kernel<<<NTOK / MTILE, TPB, SMEM_TOTAL>>>(
        inputs, context, Wctx, Wp, bt, b1, b2, bg, bp, gam, bet, Ws, bs,
        wout, selected);
}

// round 16
// speedup vs baseline: 1.4851x; 1.1302x over previous
#include <cuda_runtime.h>
#include <cuda_fp16.h>
#include <math.h>

#define NB 64
#define NT 512
#define NVARS 16
#define VDIM 16
#define DD 64
#define NTOK (NB*NT)
#define TPB 256
#define MTILE 128
#define LN_EPS 1e-3f

typedef unsigned long long u64;
typedef unsigned int u32;

// prepped weights: per var 5 tiles x 8192B (swizzled [n][k] fp16, 128B rows)
#define WPV_BYTES 40960
__device__ __align__(16) char g_wprep[NVARS * WPV_BYTES];

// tile byte offsets within a var block
#define WT_OFF 0
#define WP_OFF 8192
#define W1_OFF 16384
#define W2_OFF 24576
#define WG_OFF 32768
// smem byte offsets
#define WBUF0    0           // 40960
#define WBUF1    40960
#define BIAS_ALL 81920       // 16 x 7 x 64 floats = 28672
#define CPROJ_O  110592      // 16 x 64 floats = 4096
#define WSEL_O   114688      // 128 x 16 floats = 8192
#define CTX_O    122880      // 64 floats
#define SMEM_TOTAL 123136

// ---------------- ptx helpers ----------------
__device__ __forceinline__ u32 smem_u32(const void* p) {
    u32 a;
    asm("{ .reg .u64 t; cvta.to.shared.u64 t, %1; cvt.u32.u64 %0, t; }"
        : "=r"(a) : "l"(p));
    return a;
}

#define LDMX4(r0, r1, r2, r3, addr) \
    asm volatile("ldmatrix.sync.aligned.m8n8.x4.shared.b16 {%0,%1,%2,%3}, [%4];" \
                 : "=r"(r0), "=r"(r1), "=r"(r2), "=r"(r3) : "r"(addr))

#define CP_ASYNC16(dst, src) \
    asm volatile("cp.async.cg.shared.global [%0], [%1], 16;" :: "r"(dst), "l"(src))
#define CP_COMMIT() asm volatile("cp.async.commit_group;")
#define CP_WAIT1() asm volatile("cp.async.wait_group 1;")
#define CP_WAIT0() asm volatile("cp.async.wait_group 0;")

__device__ __forceinline__ void mma16816(float* d, u32 a0, u32 a1, u32 a2, u32 a3,
                                         u32 b0, u32 b1) {
    asm volatile(
        "mma.sync.aligned.m16n8k16.row.col.f32.f16.f16.f32 "
        "{%0,%1,%2,%3},{%4,%5,%6,%7},{%8,%9},{%0,%1,%2,%3};"
        : "+f"(d[0]), "+f"(d[1]), "+f"(d[2]), "+f"(d[3])
        : "r"(a0), "r"(a1), "r"(a2), "r"(a3), "r"(b0), "r"(b1));
}

// pack (e0, e1) -> f16x2 with e0 in LOW half
__device__ __forceinline__ u32 pkpair(float e0, float e1) {
    u32 r;
    asm("cvt.rn.f16x2.f32 %0, %1, %2;" : "=r"(r) : "f"(e1), "f"(e0));
    return r;
}
__device__ __forceinline__ float flo(u32 r) {
    __half2 h = *reinterpret_cast<__half2*>(&r);
    return __low2float(h);
}
__device__ __forceinline__ float fhi(u32 r) {
    __half2 h = *reinterpret_cast<__half2*>(&r);
    return __high2float(h);
}
__device__ __forceinline__ u32 pklo(u32 h, float e0, float e1) {
    return pkpair(e0 - flo(h), e1 - fhi(h));
}

// sigmoid via single-MUFU tanh.approx: sigm(x) = 0.5*tanh(x/2) + 0.5
__device__ __forceinline__ float sigm(float x) {
    float t;
    asm("tanh.approx.f32 %0, %1;" : "=f"(t) : "f"(x * 0.5f));
    return fmaf(0.5f, t, 0.5f);
}

__device__ __forceinline__ void d_to_frag(const float* D, u32* fh, u32* fl) {
#pragma unroll
    for (int kt = 0; kt < 4; kt++) {
        const float* d0 = D + (2 * kt) * 4;
        const float* d1 = D + (2 * kt + 1) * 4;
        u32 h;
        h = pkpair(d0[0], d0[1]); fh[4*kt+0] = h; fl[4*kt+0] = pklo(h, d0[0], d0[1]);
        h = pkpair(d0[2], d0[3]); fh[4*kt+1] = h; fl[4*kt+1] = pklo(h, d0[2], d0[3]);
        h = pkpair(d1[0], d1[1]); fh[4*kt+2] = h; fl[4*kt+2] = pklo(h, d1[0], d1[1]);
        h = pkpair(d1[2], d1[3]); fh[4*kt+3] = h; fl[4*kt+3] = pklo(h, d1[2], d1[3]);
    }
}

// hi-only fragment conversion (for h2 feeding the gate layer)
__device__ __forceinline__ void d_to_frag_hi(const float* D, u32* fh) {
#pragma unroll
    for (int kt = 0; kt < 4; kt++) {
        const float* d0 = D + (2 * kt) * 4;
        const float* d1 = D + (2 * kt + 1) * 4;
        fh[4*kt+0] = pkpair(d0[0], d0[1]);
        fh[4*kt+1] = pkpair(d0[2], d0[3]);
        fh[4*kt+2] = pkpair(d1[0], d1[1]);
        fh[4*kt+3] = pkpair(d1[2], d1[3]);
    }
}

__device__ __forceinline__ void d_init(float* D, const float* bvec, int tig) {
#pragma unroll
    for (int j = 0; j < 8; j++) {
        float2 bv = *(const float2*)(bvec + 8 * j + 2 * tig);
        D[4*j+0] = bv.x; D[4*j+1] = bv.y; D[4*j+2] = bv.x; D[4*j+3] = bv.y;
    }
}

// single layer, A split: D += (Ahi+Alo)@B^T (4 MMAs per kt,p)
__device__ __forceinline__ void do_layer(u32 base,
                                         const u32* fh, const u32* fl,
                                         float* D, int rowin, int m) {
    const u32 sw = (u32)(rowin << 4);
    const u32 rb = (u32)((m >> 1) * 1024 + rowin * 128);
#pragma unroll
    for (int kt = 0; kt < 4; kt++) {
        u32 csw = ((u32)(32 * kt + 16 * (m & 1))) ^ sw;
        const u32* ah = fh + 4 * kt;
        const u32* al = fl + 4 * kt;
#pragma unroll
        for (int p = 0; p < 4; p++) {
            u32 off = rb + (u32)(p * 2048) + csw;
            u32 b0, b1, b2, b3;
            LDMX4(b0, b1, b2, b3, base + off);
            mma16816(D + 8*p,     ah[0], ah[1], ah[2], ah[3], b0, b1);
            mma16816(D + 8*p + 4, ah[0], ah[1], ah[2], ah[3], b2, b3);
            mma16816(D + 8*p,     al[0], al[1], al[2], al[3], b0, b1);
            mma16816(D + 8*p + 4, al[0], al[1], al[2], al[3], b2, b3);
        }
    }
}

// hi-only layer (gate path): D += Ahi@B^T (2 MMAs per kt,p)
__device__ __forceinline__ void do_layer_hi(u32 base, const u32* fh,
                                            float* D, int rowin, int m) {
    const u32 sw = (u32)(rowin << 4);
    const u32 rb = (u32)((m >> 1) * 1024 + rowin * 128);
#pragma unroll
    for (int kt = 0; kt < 4; kt++) {
        u32 csw = ((u32)(32 * kt + 16 * (m & 1))) ^ sw;
        const u32* ah = fh + 4 * kt;
#pragma unroll
        for (int p = 0; p < 4; p++) {
            u32 off = rb + (u32)(p * 2048) + csw;
            u32 b0, b1, b2, b3;
            LDMX4(b0, b1, b2, b3, base + off);
            mma16816(D + 8*p,     ah[0], ah[1], ah[2], ah[3], b0, b1);
            mma16816(D + 8*p + 4, ah[0], ah[1], ah[2], ah[3], b2, b3);
        }
    }
}

// fused dual layer: Dr += A@Wp^T, D += A@W1^T, MMAs alternating chains
__device__ __forceinline__ void do_layer2(u32 wp, u32 w1,
                                          const u32* fh, const u32* fl,
                                          float* Dr, float* D, int rowin, int m) {
    const u32 sw = (u32)(rowin << 4);
    const u32 rb = (u32)((m >> 1) * 1024 + rowin * 128);
#pragma unroll
    for (int kt = 0; kt < 4; kt++) {
        u32 csw = ((u32)(32 * kt + 16 * (m & 1))) ^ sw;
        const u32* ah = fh + 4 * kt;
        const u32* al = fl + 4 * kt;
#pragma unroll
        for (int p = 0; p < 4; p++) {
            u32 off = rb + (u32)(p * 2048) + csw;
            u32 p0, p1, p2, p3, o0, o1, o2, o3;
            LDMX4(p0, p1, p2, p3, wp + off);
            LDMX4(o0, o1, o2, o3, w1 + off);
            mma16816(Dr + 8*p,     ah[0], ah[1], ah[2], ah[3], p0, p1);
            mma16816(D  + 8*p,     ah[0], ah[1], ah[2], ah[3], o0, o1);
            mma16816(Dr + 8*p + 4, ah[0], ah[1], ah[2], ah[3], p2, p3);
            mma16816(D  + 8*p + 4, ah[0], ah[1], ah[2], ah[3], o2, o3);
            mma16816(Dr + 8*p,     al[0], al[1], al[2], al[3], p0, p1);
            mma16816(D  + 8*p,     al[0], al[1], al[2], al[3], o0, o1);
            mma16816(Dr + 8*p + 4, al[0], al[1], al[2], al[3], p2, p3);
            mma16816(D  + 8*p + 4, al[0], al[1], al[2], al[3], o2, o3);
        }
    }
}

__device__ __forceinline__ void prefetch_var(u32 dst, const char* src, int tid) {
#pragma unroll
    for (int i = 0; i < 10; i++) {
        int idx = (tid + i * 256) * 16;
        CP_ASYNC16(dst + (u32)idx, src + idx);
    }
}

// ---------------------------------------------------------------------------
// prep: transpose + fp16 convert into swizzled [n][k] tiles; grid (NVARS, 5)
// ---------------------------------------------------------------------------
__global__ void prep_weights_kernel(const float* __restrict__ Wt,
                                    const float* __restrict__ Wp,
                                    const float* __restrict__ W1,
                                    const float* __restrict__ W2,
                                    const float* __restrict__ Wg) {
    int n = blockIdx.x, m = blockIdx.y;
    char* dst = g_wprep + (size_t)n * WPV_BYTES;
    if (m == 0) {
        for (int e = threadIdx.x; e < VDIM * DD; e += blockDim.x) {
            int d = e & 63, v = e >> 6;
            float w = Wt[(size_t)n * VDIM * DD + v * DD + d];
            u32 cs = (u32)(16 * (v >> 3));
            u32 swx = ((u32)(d & 7)) << 4;
            u32 addr = (u32)(d * 128) + (cs ^ swx) + (u32)((v & 7) * 2);
            *(__half*)(dst + WT_OFF + addr) = __float2half(w);
        }
    } else {
        const float* srcs[4] = {Wp + (size_t)n * DD * DD, W1 + (size_t)n * DD * DD,
                                W2 + (size_t)n * DD * DD, Wg + (size_t)n * DD * DD};
        const int toff[4] = {WP_OFF, W1_OFF, W2_OFF, WG_OFF};
        int mm = m - 1;
        const float* s = srcs[mm];
        char* th = dst + toff[mm];
        for (int e = threadIdx.x; e < DD * DD; e += blockDim.x) {
            int d = e & 63, k = e >> 6;
            float w = s[k * DD + d];
            u32 cs = (u32)(16 * (k >> 3));
            u32 swx = ((u32)(d & 7)) << 4;
            u32 addr = (u32)(d * 128) + (cs ^ swx) + (u32)((k & 7) * 2);
            *(__half*)(th + addr) = __float2half(w);
        }
    }
}

// ---------------------------------------------------------------------------
// main
// ---------------------------------------------------------------------------
__global__ __launch_bounds__(TPB, 1) void vsn_mma_kernel(
    const float* __restrict__ inputs, const float* __restrict__ context,
    const float* __restrict__ Wctx, const float* __restrict__ Wp_g,
    const float* __restrict__ bt, const float* __restrict__ b1,
    const float* __restrict__ b2, const float* __restrict__ bg,
    const float* __restrict__ bp,
    const float* __restrict__ gamma_, const float* __restrict__ beta_,
    const float* __restrict__ Ws, const float* __restrict__ bs,
    float* __restrict__ wout, float* __restrict__ selected) {
    extern __shared__ __align__(128) char sm[];
    const int tid = threadIdx.x;
    const int wid = tid >> 5, lane = tid & 31;
    const int gid = lane >> 2, tig = lane & 3;
    const int rowin = lane & 7, mq = lane >> 3;
    const int row0 = wid * 16 + gid, row1 = row0 + 8;
    const int base = blockIdx.x * MTILE;
    const int bb = base / NT;
    const int tok0 = base + row0, tok1 = base + row1;

    const u32 smb = smem_u32(sm);
    float* bias_all = (float*)(sm + BIAS_ALL);
    float* cproj_s = (float*)(sm + CPROJ_O);
    float* wsel_s  = (float*)(sm + WSEL_O);
    float* ctx_s   = (float*)(sm + CTX_O);

    // prefetch var 0 weights
    prefetch_var(smb + WBUF0, g_wprep, tid);
    CP_COMMIT();

    // stage Ws (WBUF1, free until var-1 prefetch), ctx, biases
    {
        const float4* s = (const float4*)Ws;
        float4* d = (float4*)(sm + WBUF1);
        for (int i = tid; i < 1024; i += TPB) d[i] = s[i];
        if (tid < DD) ctx_s[tid] = context[(size_t)bb * DD + tid];
        const float* bsrc[7] = {bt, b1, b2, bg, bp, gamma_, beta_};
        for (int i = tid; i < NVARS * 7 * DD; i += TPB) {
            int n = i / 448, r = i - n * 448, s7 = r >> 6, d7 = r & 63;
            bias_all[i] = bsrc[s7][n * DD + d7];
        }
    }
    __syncthreads();

    if (tid < 128) {
        // softmax for token base+tid
        int token = base + tid;
        const float4* xp = (const float4*)(inputs + (size_t)token * 256);
        const float* ws_s = (const float*)(sm + WBUF1);
        float l[16];
#pragma unroll
        for (int i = 0; i < 16; i++) l[i] = bs[i];
#pragma unroll 4
        for (int f4 = 0; f4 < 64; ++f4) {
            float4 xv = xp[f4];
            const float* wr = ws_s + f4 * 64;
#pragma unroll
            for (int c = 0; c < 4; c++) {
                float x = (c == 0) ? xv.x : (c == 1) ? xv.y : (c == 2) ? xv.z : xv.w;
                const float* w = wr + c * 16;
#pragma unroll
                for (int i = 0; i < 16; i++) l[i] = fmaf(x, w[i], l[i]);
            }
        }
        float mx = l[0];
#pragma unroll
        for (int i = 1; i < 16; i++) mx = fmaxf(mx, l[i]);
        float s = 0.f;
#pragma unroll
        for (int i = 0; i < 16; i++) { l[i] = __expf(l[i] - mx); s += l[i]; }
        float inv = __fdividef(1.f, s);
        float4* gp = (float4*)(wout + (size_t)token * 16);
        float4* sp = (float4*)(wsel_s + tid * 16);
#pragma unroll
        for (int j = 0; j < 4; j++) {
            float4 o = make_float4(l[4*j] * inv, l[4*j+1] * inv,
                                   l[4*j+2] * inv, l[4*j+3] * inv);
            gp[j] = o;
            sp[j] = o;
        }
    } else {
        // cproj: 128 threads x 8 outputs
        int idx = tid - 128;
        int n = idx >> 3, e0 = (idx & 7) * 8;
        const float* W = Wctx + (size_t)n * DD * DD + e0;
        float acc[8];
#pragma unroll
        for (int i = 0; i < 8; i++) acc[i] = 0.f;
#pragma unroll 8
        for (int d = 0; d < DD; ++d) {
            float c = ctx_s[d];
            float4 w0 = *(const float4*)(W + d * DD);
            float4 w1 = *(const float4*)(W + d * DD + 4);
            acc[0] = fmaf(c, w0.x, acc[0]); acc[1] = fmaf(c, w0.y, acc[1]);
            acc[2] = fmaf(c, w0.z, acc[2]); acc[3] = fmaf(c, w0.w, acc[3]);
            acc[4] = fmaf(c, w1.x, acc[4]); acc[5] = fmaf(c, w1.y, acc[5]);
            acc[6] = fmaf(c, w1.z, acc[6]); acc[7] = fmaf(c, w1.w, acc[7]);
        }
        float4* cp = (float4*)(cproj_s + n * DD + e0);
        cp[0] = make_float4(acc[0], acc[1], acc[2], acc[3]);
        cp[1] = make_float4(acc[4], acc[5], acc[6], acc[7]);
    }
    __syncthreads();

    // phase 2: bp' = bp - cproj @ Wp
    {
        int i0 = tid * 4;
        int n = i0 >> 6, e = i0 & 63;
        const float* W = Wp_g + (size_t)n * DD * DD + e;
        const float* cp = cproj_s + n * DD;
        float a0 = 0.f, a1 = 0.f, a2 = 0.f, a3 = 0.f;
#pragma unroll 8
        for (int d = 0; d < DD; d++) {
            float c = cp[d];
            float4 w = *(const float4*)(W + d * DD);
            a0 = fmaf(c, w.x, a0); a1 = fmaf(c, w.y, a1);
            a2 = fmaf(c, w.z, a2); a3 = fmaf(c, w.w, a3);
        }
        float* dstp = bias_all + n * 448 + 4 * DD + e;
        dstp[0] -= a0; dstp[1] -= a1; dstp[2] -= a2; dstp[3] -= a3;
    }
    __syncthreads();

    float sel[32];
#pragma unroll
    for (int i = 0; i < 32; i++) sel[i] = 0.f;

    for (int n = 0; n < NVARS; ++n) {
        if (n < NVARS - 1) {
            prefetch_var(smb + (((n + 1) & 1) ? WBUF1 : WBUF0),
                         g_wprep + (size_t)(n + 1) * WPV_BYTES, tid);
            CP_COMMIT();
            CP_WAIT1();
        } else {
            CP_WAIT0();
        }
        __syncthreads();

        const u32 wb = smb + ((n & 1) ? WBUF1 : WBUF0);
        const float* bv = bias_all + n * 448;

        // ---- layer 1: t = x @ Wt + bt (k=16) ----
        float D[32];
        d_init(D, bv + 0 * DD, tig);
        {
            const float* xb0 = inputs + (size_t)tok0 * 256 + n * VDIM;
            const float* xb1 = inputs + (size_t)tok1 * 256 + n * VDIM;
            float2 x00 = *(const float2*)(xb0 + 2 * tig);
            float2 x10 = *(const float2*)(xb1 + 2 * tig);
            float2 x01 = *(const float2*)(xb0 + 8 + 2 * tig);
            float2 x11 = *(const float2*)(xb1 + 8 + 2 * tig);
            u32 axh[4], axl[4];
            axh[0] = pkpair(x00.x, x00.y); axl[0] = pklo(axh[0], x00.x, x00.y);
            axh[1] = pkpair(x10.x, x10.y); axl[1] = pklo(axh[1], x10.x, x10.y);
            axh[2] = pkpair(x01.x, x01.y); axl[2] = pklo(axh[2], x01.x, x01.y);
            axh[3] = pkpair(x11.x, x11.y); axl[3] = pklo(axh[3], x11.x, x11.y);

            const u32 sw = (u32)(rowin << 4);
            const u32 rb = (u32)((mq >> 1) * 1024 + rowin * 128);
            u32 csh = ((u32)(16 * (mq & 1))) ^ sw;
#pragma unroll
            for (int p = 0; p < 4; p++) {
                u32 off = rb + (u32)(p * 2048) + csh;
                u32 b0, b1, b2, b3;
                LDMX4(b0, b1, b2, b3, wb + WT_OFF + off);
                mma16816(D + 8*p,     axh[0], axh[1], axh[2], axh[3], b0, b1);
                mma16816(D + 8*p + 4, axh[0], axh[1], axh[2], axh[3], b2, b3);
                mma16816(D + 8*p,     axl[0], axl[1], axl[2], axl[3], b0, b1);
                mma16816(D + 8*p + 4, axl[0], axl[1], axl[2], axl[3], b2, b3);
            }
        }

        // ---- a = t + cproj ; one frag conversion feeds Wp AND W1 ----
#pragma unroll
        for (int j = 0; j < 8; j++) {
            float2 cp = *(const float2*)(cproj_s + n * DD + 8 * j + 2 * tig);
            D[4*j+0] += cp.x; D[4*j+1] += cp.y;
            D[4*j+2] += cp.x; D[4*j+3] += cp.y;
        }
        u32 fh[16], fl[16];
        d_to_frag(D, fh, fl);      // a fragments

        // ---- fused: residual = a@Wp + bp'  ||  h1pre = a@W1 + b1 ----
        float Dres[32];
        d_init(Dres, bv + 4 * DD, tig);
        d_init(D, bv + 1 * DD, tig);
        do_layer2(wb + WP_OFF, wb + W1_OFF, fh, fl, Dres, D, rowin, mq);

        // ---- h1 = elu(h1pre) ----
#pragma unroll
        for (int i = 0; i < 32; i++) {
            float x = D[i];
            D[i] = x > 0.f ? x : (__expf(x) - 1.f);
        }
        d_to_frag(D, fh, fl);

        // ---- h2 = h1 @ W2 + b2 ----
        d_init(D, bv + 2 * DD, tig);
        do_layer(wb + W2_OFF, fh, fl, D, rowin, mq);
        d_to_frag_hi(D, fh);       // h2 fragments (hi only; gate path + epilogue)

        // ---- gate logits = h2 @ Wg + bg (hi-only A) ----
        d_init(D, bv + 3 * DD, tig);
        do_layer_hi(wb + WG_OFF, fh, D, rowin, mq);

        // ---- y, LN, weighted select ----
        float sum0 = 0.f, sq0 = 0.f, sum1 = 0.f, sq1 = 0.f;
#pragma unroll
        for (int j = 0; j < 8; j++) {
            int o = 4 * (j >> 1) + 2 * (j & 1);
            u32 h0 = fh[o], h1r = fh[o + 1];
            float h2a = flo(h0), h2b = fhi(h0);
            float h2c = flo(h1r), h2d = fhi(h1r);
            float y0 = fmaf(sigm(D[4*j+0]), h2a, Dres[4*j+0]);
            float y1 = fmaf(sigm(D[4*j+1]), h2b, Dres[4*j+1]);
            float y2 = fmaf(sigm(D[4*j+2]), h2c, Dres[4*j+2]);
            float y3 = fmaf(sigm(D[4*j+3]), h2d, Dres[4*j+3]);
            D[4*j+0] = y0; D[4*j+1] = y1; D[4*j+2] = y2; D[4*j+3] = y3;
            sum0 += y0 + y1; sq0 = fmaf(y0, y0, fmaf(y1, y1, sq0));
            sum1 += y2 + y3; sq1 = fmaf(y2, y2, fmaf(y3, y3, sq1));
        }
        sum0 += __shfl_xor_sync(0xffffffffu, sum0, 1);
        sum0 += __shfl_xor_sync(0xffffffffu, sum0, 2);
        sq0  += __shfl_xor_sync(0xffffffffu, sq0, 1);
        sq0  += __shfl_xor_sync(0xffffffffu, sq0, 2);
        sum1 += __shfl_xor_sync(0xffffffffu, sum1, 1);
        sum1 += __shfl_xor_sync(0xffffffffu, sum1, 2);
        sq1  += __shfl_xor_sync(0xffffffffu, sq1, 1);
        sq1  += __shfl_xor_sync(0xffffffffu, sq1, 2);
        float mu0 = sum0 * (1.f / 64.f);
        float rs0 = rsqrtf(sq0 * (1.f / 64.f) - mu0 * mu0 + LN_EPS);
        float mu1 = sum1 * (1.f / 64.f);
        float rs1 = rsqrtf(sq1 * (1.f / 64.f) - mu1 * mu1 + LN_EPS);
        float w0 = wsel_s[row0 * NVARS + n];
        float w1 = wsel_s[row1 * NVARS + n];
#pragma unroll
        for (int j = 0; j < 8; j++) {
            float2 gm = *(const float2*)(bv + 5 * DD + 8 * j + 2 * tig);
            float2 be = *(const float2*)(bv + 6 * DD + 8 * j + 2 * tig);
            float yn0 = fmaf((D[4*j+0] - mu0) * rs0, gm.x, be.x);
            float yn1 = fmaf((D[4*j+1] - mu0) * rs0, gm.y, be.y);
            float yn2 = fmaf((D[4*j+2] - mu1) * rs1, gm.x, be.x);
            float yn3 = fmaf((D[4*j+3] - mu1) * rs1, gm.y, be.y);
            sel[4*j+0] = fmaf(w0, yn0, sel[4*j+0]);
            sel[4*j+1] = fmaf(w0, yn1, sel[4*j+1]);
            sel[4*j+2] = fmaf(w1, yn2, sel[4*j+2]);
            sel[4*j+3] = fmaf(w1, yn3, sel[4*j+3]);
        }
        __syncthreads();
    }

    // ---- output ----
#pragma unroll
    for (int j = 0; j < 8; j++) {
        *(float2*)(selected + (size_t)tok0 * DD + 8 * j + 2 * tig)
            = make_float2(sel[4*j+0], sel[4*j+1]);
        *(float2*)(selected + (size_t)tok1 * DD + 8 * j + 2 * tig)
            = make_float2(sel[4*j+2], sel[4*j+3]);
    }
}

// ---------------------------------------------------------------------------
extern "C" void kernel_launch(void* const* d_in, const int* in_sizes, int n_in,
                              void* d_out, int out_size) {
    const float* inputs  = (const float*)d_in[0];
    const float* context = (const float*)d_in[1];
    const float* Wt   = (const float*)d_in[2];
    const float* bt   = (const float*)d_in[3];
    const float* Wctx = (const float*)d_in[4];
    const float* W1   = (const float*)d_in[5];
    const float* b1   = (const float*)d_in[6];
    const float* W2   = (const float*)d_in[7];
    const float* b2   = (const float*)d_in[8];
    const float* Wg   = (const float*)d_in[9];
    const float* bg   = (const float*)d_in[10];
    const float* Wp   = (const float*)d_in[11];
    const float* bp   = (const float*)d_in[12];
    const float* gam  = (const float*)d_in[13];
    const float* bet  = (const float*)d_in[14];
    const float* Ws   = (const float*)d_in[15];
    const float* bs   = (const float*)d_in[16];

    float* selected = (float*)d_out;
    float* wout = selected + (size_t)NTOK * DD;

    prep_weights_kernel<<<dim3(NVARS, 5), 256>>>(Wt, Wp, W1, W2, Wg);

    cudaFuncSetAttribute(vsn_mma_kernel,
                         cudaFuncAttributeMaxDynamicSharedMemorySize, SMEM_TOTAL);
    vsn_mma_kernel<<<NTOK / MTILE, TPB, SMEM_TOTAL>>>(
        inputs, context, Wctx, Wp, bt, b1, b2, bg, bp, gam, bet, Ws, bs,
        wout, selected);
}

// round 17
// speedup vs baseline: 1.6711x; 1.1253x over previous
#include <cuda_runtime.h>
#include <cuda_fp16.h>
#include <math.h>

#define NB 64
#define NT 512
#define NVARS 16
#define VDIM 16
#define DD 64
#define NTOK (NB*NT)
#define TPB 256
#define MTILE 128
#define LN_EPS 1e-3f

typedef unsigned long long u64;
typedef unsigned int u32;

// prepped weights: per var 5 tiles x 8192B (swizzled [n][k] fp16, 128B rows)
#define WPV_BYTES 40960
__device__ __align__(16) char g_wprep[NVARS * WPV_BYTES];

// tile byte offsets within a var block
#define WT_OFF 0
#define WP_OFF 8192
#define W1_OFF 16384
#define W2_OFF 24576
#define WG_OFF 32768
// smem byte offsets
#define WBUF0    0           // 40960
#define WBUF1    40960
#define BIAS_ALL 81920       // 16 x 7 x 64 floats = 28672
#define CPROJ_O  110592      // 16 x 64 floats = 4096
#define WSEL_O   114688      // 128 x 16 floats = 8192
#define CTX_O    122880      // 64 floats
#define SMEM_TOTAL 123136

// ---------------- ptx helpers ----------------
__device__ __forceinline__ u32 smem_u32(const void* p) {
    u32 a;
    asm("{ .reg .u64 t; cvta.to.shared.u64 t, %1; cvt.u32.u64 %0, t; }"
        : "=r"(a) : "l"(p));
    return a;
}

#define LDMX4(r0, r1, r2, r3, addr) \
    asm volatile("ldmatrix.sync.aligned.m8n8.x4.shared.b16 {%0,%1,%2,%3}, [%4];" \
                 : "=r"(r0), "=r"(r1), "=r"(r2), "=r"(r3) : "r"(addr))

#define CP_ASYNC16(dst, src) \
    asm volatile("cp.async.cg.shared.global [%0], [%1], 16;" :: "r"(dst), "l"(src))
#define CP_COMMIT() asm volatile("cp.async.commit_group;")
#define CP_WAIT1() asm volatile("cp.async.wait_group 1;")
#define CP_WAIT0() asm volatile("cp.async.wait_group 0;")

__device__ __forceinline__ void mma16816(float* d, u32 a0, u32 a1, u32 a2, u32 a3,
                                         u32 b0, u32 b1) {
    asm volatile(
        "mma.sync.aligned.m16n8k16.row.col.f32.f16.f16.f32 "
        "{%0,%1,%2,%3},{%4,%5,%6,%7},{%8,%9},{%0,%1,%2,%3};"
        : "+f"(d[0]), "+f"(d[1]), "+f"(d[2]), "+f"(d[3])
        : "r"(a0), "r"(a1), "r"(a2), "r"(a3), "r"(b0), "r"(b1));
}

// pack (e0, e1) -> f16x2 with e0 in LOW half
__device__ __forceinline__ u32 pkpair(float e0, float e1) {
    u32 r;
    asm("cvt.rn.f16x2.f32 %0, %1, %2;" : "=r"(r) : "f"(e1), "f"(e0));
    return r;
}
__device__ __forceinline__ float flo(u32 r) {
    __half2 h = *reinterpret_cast<__half2*>(&r);
    return __low2float(h);
}
__device__ __forceinline__ float fhi(u32 r) {
    __half2 h = *reinterpret_cast<__half2*>(&r);
    return __high2float(h);
}
__device__ __forceinline__ u32 pklo(u32 h, float e0, float e1) {
    return pkpair(e0 - flo(h), e1 - fhi(h));
}

// sigmoid via single-MUFU tanh.approx
__device__ __forceinline__ float sigm(float x) {
    float t;
    asm("tanh.approx.f32 %0, %1;" : "=f"(t) : "f"(x * 0.5f));
    return fmaf(0.5f, t, 0.5f);
}

// hi-only fragment conversion
__device__ __forceinline__ void d_to_frag_hi(const float* D, u32* fh) {
#pragma unroll
    for (int kt = 0; kt < 4; kt++) {
        const float* d0 = D + (2 * kt) * 4;
        const float* d1 = D + (2 * kt + 1) * 4;
        fh[4*kt+0] = pkpair(d0[0], d0[1]);
        fh[4*kt+1] = pkpair(d0[2], d0[3]);
        fh[4*kt+2] = pkpair(d1[0], d1[1]);
        fh[4*kt+3] = pkpair(d1[2], d1[3]);
    }
}

__device__ __forceinline__ void d_init(float* D, const float* bvec, int tig) {
#pragma unroll
    for (int j = 0; j < 8; j++) {
        float2 bv = *(const float2*)(bvec + 8 * j + 2 * tig);
        D[4*j+0] = bv.x; D[4*j+1] = bv.y; D[4*j+2] = bv.x; D[4*j+3] = bv.y;
    }
}

// hi-only layer: D += Ahi@B^T (2 MMAs per kt,p)
__device__ __forceinline__ void do_layer_hi(u32 base, const u32* fh,
                                            float* D, int rowin, int m) {
    const u32 sw = (u32)(rowin << 4);
    const u32 rb = (u32)((m >> 1) * 1024 + rowin * 128);
#pragma unroll
    for (int kt = 0; kt < 4; kt++) {
        u32 csw = ((u32)(32 * kt + 16 * (m & 1))) ^ sw;
        const u32* ah = fh + 4 * kt;
#pragma unroll
        for (int p = 0; p < 4; p++) {
            u32 off = rb + (u32)(p * 2048) + csw;
            u32 b0, b1, b2, b3;
            LDMX4(b0, b1, b2, b3, base + off);
            mma16816(D + 8*p,     ah[0], ah[1], ah[2], ah[3], b0, b1);
            mma16816(D + 8*p + 4, ah[0], ah[1], ah[2], ah[3], b2, b3);
        }
    }
}

// fused dual hi-only layer: Dr += A@Wp^T, D += A@W1^T, alternating chains
__device__ __forceinline__ void do_layer2_hi(u32 wp, u32 w1, const u32* fh,
                                             float* Dr, float* D, int rowin, int m) {
    const u32 sw = (u32)(rowin << 4);
    const u32 rb = (u32)((m >> 1) * 1024 + rowin * 128);
#pragma unroll
    for (int kt = 0; kt < 4; kt++) {
        u32 csw = ((u32)(32 * kt + 16 * (m & 1))) ^ sw;
        const u32* ah = fh + 4 * kt;
#pragma unroll
        for (int p = 0; p < 4; p++) {
            u32 off = rb + (u32)(p * 2048) + csw;
            u32 p0, p1, p2, p3, o0, o1, o2, o3;
            LDMX4(p0, p1, p2, p3, wp + off);
            LDMX4(o0, o1, o2, o3, w1 + off);
            mma16816(Dr + 8*p,     ah[0], ah[1], ah[2], ah[3], p0, p1);
            mma16816(D  + 8*p,     ah[0], ah[1], ah[2], ah[3], o0, o1);
            mma16816(Dr + 8*p + 4, ah[0], ah[1], ah[2], ah[3], p2, p3);
            mma16816(D  + 8*p + 4, ah[0], ah[1], ah[2], ah[3], o2, o3);
        }
    }
}

__device__ __forceinline__ void prefetch_var(u32 dst, const char* src, int tid) {
#pragma unroll
    for (int i = 0; i < 10; i++) {
        int idx = (tid + i * 256) * 16;
        CP_ASYNC16(dst + (u32)idx, src + idx);
    }
}

// ---------------------------------------------------------------------------
// prep: transpose + fp16 convert into swizzled [n][k] tiles; grid (NVARS, 5)
// ---------------------------------------------------------------------------
__global__ void prep_weights_kernel(const float* __restrict__ Wt,
                                    const float* __restrict__ Wp,
                                    const float* __restrict__ W1,
                                    const float* __restrict__ W2,
                                    const float* __restrict__ Wg) {
    int n = blockIdx.x, m = blockIdx.y;
    char* dst = g_wprep + (size_t)n * WPV_BYTES;
    if (m == 0) {
        for (int e = threadIdx.x; e < VDIM * DD; e += blockDim.x) {
            int d = e & 63, v = e >> 6;
            float w = Wt[(size_t)n * VDIM * DD + v * DD + d];
            u32 cs = (u32)(16 * (v >> 3));
            u32 swx = ((u32)(d & 7)) << 4;
            u32 addr = (u32)(d * 128) + (cs ^ swx) + (u32)((v & 7) * 2);
            *(__half*)(dst + WT_OFF + addr) = __float2half(w);
        }
    } else {
        const float* srcs[4] = {Wp + (size_t)n * DD * DD, W1 + (size_t)n * DD * DD,
                                W2 + (size_t)n * DD * DD, Wg + (size_t)n * DD * DD};
        const int toff[4] = {WP_OFF, W1_OFF, W2_OFF, WG_OFF};
        int mm = m - 1;
        const float* s = srcs[mm];
        char* th = dst + toff[mm];
        for (int e = threadIdx.x; e < DD * DD; e += blockDim.x) {
            int d = e & 63, k = e >> 6;
            float w = s[k * DD + d];
            u32 cs = (u32)(16 * (k >> 3));
            u32 swx = ((u32)(d & 7)) << 4;
            u32 addr = (u32)(d * 128) + (cs ^ swx) + (u32)((k & 7) * 2);
            *(__half*)(th + addr) = __float2half(w);
        }
    }
}

// ---------------------------------------------------------------------------
// main
// ---------------------------------------------------------------------------
__global__ __launch_bounds__(TPB, 1) void vsn_mma_kernel(
    const float* __restrict__ inputs, const float* __restrict__ context,
    const float* __restrict__ Wctx, const float* __restrict__ Wp_g,
    const float* __restrict__ bt, const float* __restrict__ b1,
    const float* __restrict__ b2, const float* __restrict__ bg,
    const float* __restrict__ bp,
    const float* __restrict__ gamma_, const float* __restrict__ beta_,
    const float* __restrict__ Ws, const float* __restrict__ bs,
    float* __restrict__ wout, float* __restrict__ selected) {
    extern __shared__ __align__(128) char sm[];
    const int tid = threadIdx.x;
    const int wid = tid >> 5, lane = tid & 31;
    const int gid = lane >> 2, tig = lane & 3;
    const int rowin = lane & 7, mq = lane >> 3;
    const int row0 = wid * 16 + gid, row1 = row0 + 8;
    const int base = blockIdx.x * MTILE;
    const int bb = base / NT;
    const int tok0 = base + row0, tok1 = base + row1;

    const u32 smb = smem_u32(sm);
    float* bias_all = (float*)(sm + BIAS_ALL);
    float* cproj_s = (float*)(sm + CPROJ_O);
    float* wsel_s  = (float*)(sm + WSEL_O);
    float* ctx_s   = (float*)(sm + CTX_O);

    // prefetch var 0 weights
    prefetch_var(smb + WBUF0, g_wprep, tid);
    CP_COMMIT();

    // stage Ws (WBUF1, free until var-1 prefetch), ctx, biases
    {
        const float4* s = (const float4*)Ws;
        float4* d = (float4*)(sm + WBUF1);
        for (int i = tid; i < 1024; i += TPB) d[i] = s[i];
        if (tid < DD) ctx_s[tid] = context[(size_t)bb * DD + tid];
        const float* bsrc[7] = {bt, b1, b2, bg, bp, gamma_, beta_};
        for (int i = tid; i < NVARS * 7 * DD; i += TPB) {
            int n = i / 448, r = i - n * 448, s7 = r >> 6, d7 = r & 63;
            bias_all[i] = bsrc[s7][n * DD + d7];
        }
    }
    __syncthreads();

    if (tid < 128) {
        // softmax for token base+tid
        int token = base + tid;
        const float4* xp = (const float4*)(inputs + (size_t)token * 256);
        const float* ws_s = (const float*)(sm + WBUF1);
        float l[16];
#pragma unroll
        for (int i = 0; i < 16; i++) l[i] = bs[i];
#pragma unroll 4
        for (int f4 = 0; f4 < 64; ++f4) {
            float4 xv = xp[f4];
            const float* wr = ws_s + f4 * 64;
#pragma unroll
            for (int c = 0; c < 4; c++) {
                float x = (c == 0) ? xv.x : (c == 1) ? xv.y : (c == 2) ? xv.z : xv.w;
                const float* w = wr + c * 16;
#pragma unroll
                for (int i = 0; i < 16; i++) l[i] = fmaf(x, w[i], l[i]);
            }
        }
        float mx = l[0];
#pragma unroll
        for (int i = 1; i < 16; i++) mx = fmaxf(mx, l[i]);
        float s = 0.f;
#pragma unroll
        for (int i = 0; i < 16; i++) { l[i] = __expf(l[i] - mx); s += l[i]; }
        float inv = __fdividef(1.f, s);
        float4* gp = (float4*)(wout + (size_t)token * 16);
        float4* sp = (float4*)(wsel_s + tid * 16);
#pragma unroll
        for (int j = 0; j < 4; j++) {
            float4 o = make_float4(l[4*j] * inv, l[4*j+1] * inv,
                                   l[4*j+2] * inv, l[4*j+3] * inv);
            gp[j] = o;
            sp[j] = o;
        }
    } else {
        // cproj: 128 threads x 8 outputs
        int idx = tid - 128;
        int n = idx >> 3, e0 = (idx & 7) * 8;
        const float* W = Wctx + (size_t)n * DD * DD + e0;
        float acc[8];
#pragma unroll
        for (int i = 0; i < 8; i++) acc[i] = 0.f;
#pragma unroll 8
        for (int d = 0; d < DD; ++d) {
            float c = ctx_s[d];
            float4 w0 = *(const float4*)(W + d * DD);
            float4 w1 = *(const float4*)(W + d * DD + 4);
            acc[0] = fmaf(c, w0.x, acc[0]); acc[1] = fmaf(c, w0.y, acc[1]);
            acc[2] = fmaf(c, w0.z, acc[2]); acc[3] = fmaf(c, w0.w, acc[3]);
            acc[4] = fmaf(c, w1.x, acc[4]); acc[5] = fmaf(c, w1.y, acc[5]);
            acc[6] = fmaf(c, w1.z, acc[6]); acc[7] = fmaf(c, w1.w, acc[7]);
        }
        float4* cp = (float4*)(cproj_s + n * DD + e0);
        cp[0] = make_float4(acc[0], acc[1], acc[2], acc[3]);
        cp[1] = make_float4(acc[4], acc[5], acc[6], acc[7]);
    }
    __syncthreads();

    // phase 2: bp' = bp - cproj @ Wp
    {
        int i0 = tid * 4;
        int n = i0 >> 6, e = i0 & 63;
        const float* W = Wp_g + (size_t)n * DD * DD + e;
        const float* cp = cproj_s + n * DD;
        float a0 = 0.f, a1 = 0.f, a2 = 0.f, a3 = 0.f;
#pragma unroll 8
        for (int d = 0; d < DD; d++) {
            float c = cp[d];
            float4 w = *(const float4*)(W + d * DD);
            a0 = fmaf(c, w.x, a0); a1 = fmaf(c, w.y, a1);
            a2 = fmaf(c, w.z, a2); a3 = fmaf(c, w.w, a3);
        }
        float* dstp = bias_all + n * 448 + 4 * DD + e;
        dstp[0] -= a0; dstp[1] -= a1; dstp[2] -= a2; dstp[3] -= a3;
    }
    __syncthreads();

    float sel[32];
#pragma unroll
    for (int i = 0; i < 32; i++) sel[i] = 0.f;

    for (int n = 0; n < NVARS; ++n) {
        if (n < NVARS - 1) {
            prefetch_var(smb + (((n + 1) & 1) ? WBUF1 : WBUF0),
                         g_wprep + (size_t)(n + 1) * WPV_BYTES, tid);
            CP_COMMIT();
            CP_WAIT1();
        } else {
            CP_WAIT0();
        }
        __syncthreads();

        const u32 wb = smb + ((n & 1) ? WBUF1 : WBUF0);
        const float* bv = bias_all + n * 448;

        // ---- layer 1: t = x @ Wt + bt (k=16, x kept hi/lo split) ----
        float D[32];
        d_init(D, bv + 0 * DD, tig);
        {
            const float* xb0 = inputs + (size_t)tok0 * 256 + n * VDIM;
            const float* xb1 = inputs + (size_t)tok1 * 256 + n * VDIM;
            float2 x00 = *(const float2*)(xb0 + 2 * tig);
            float2 x10 = *(const float2*)(xb1 + 2 * tig);
            float2 x01 = *(const float2*)(xb0 + 8 + 2 * tig);
            float2 x11 = *(const float2*)(xb1 + 8 + 2 * tig);
            u32 axh[4], axl[4];
            axh[0] = pkpair(x00.x, x00.y); axl[0] = pklo(axh[0], x00.x, x00.y);
            axh[1] = pkpair(x10.x, x10.y); axl[1] = pklo(axh[1], x10.x, x10.y);
            axh[2] = pkpair(x01.x, x01.y); axl[2] = pklo(axh[2], x01.x, x01.y);
            axh[3] = pkpair(x11.x, x11.y); axl[3] = pklo(axh[3], x11.x, x11.y);

            const u32 sw = (u32)(rowin << 4);
            const u32 rb = (u32)((mq >> 1) * 1024 + rowin * 128);
            u32 csh = ((u32)(16 * (mq & 1))) ^ sw;
#pragma unroll
            for (int p = 0; p < 4; p++) {
                u32 off = rb + (u32)(p * 2048) + csh;
                u32 b0, b1, b2, b3;
                LDMX4(b0, b1, b2, b3, wb + WT_OFF + off);
                mma16816(D + 8*p,     axh[0], axh[1], axh[2], axh[3], b0, b1);
                mma16816(D + 8*p + 4, axh[0], axh[1], axh[2], axh[3], b2, b3);
                mma16816(D + 8*p,     axl[0], axl[1], axl[2], axl[3], b0, b1);
                mma16816(D + 8*p + 4, axl[0], axl[1], axl[2], axl[3], b2, b3);
            }
        }

        // ---- a = t + cproj ; hi-only frags feed Wp AND W1 ----
#pragma unroll
        for (int j = 0; j < 8; j++) {
            float2 cp = *(const float2*)(cproj_s + n * DD + 8 * j + 2 * tig);
            D[4*j+0] += cp.x; D[4*j+1] += cp.y;
            D[4*j+2] += cp.x; D[4*j+3] += cp.y;
        }
        u32 fh[16];
        d_to_frag_hi(D, fh);       // a fragments (hi only)

        // ---- fused: residual = a@Wp + bp'  ||  h1pre = a@W1 + b1 ----
        float Dres[32];
        d_init(Dres, bv + 4 * DD, tig);
        d_init(D, bv + 1 * DD, tig);
        do_layer2_hi(wb + WP_OFF, wb + W1_OFF, fh, Dres, D, rowin, mq);

        // ---- h1 = elu(h1pre) ----
#pragma unroll
        for (int i = 0; i < 32; i++) {
            float x = D[i];
            D[i] = x > 0.f ? x : (__expf(x) - 1.f);
        }
        d_to_frag_hi(D, fh);

        // ---- h2 = h1 @ W2 + b2 (hi-only) ----
        d_init(D, bv + 2 * DD, tig);
        do_layer_hi(wb + W2_OFF, fh, D, rowin, mq);
        d_to_frag_hi(D, fh);       // h2 fragments (hi only)

        // ---- gate logits = h2 @ Wg + bg (hi-only) ----
        d_init(D, bv + 3 * DD, tig);
        do_layer_hi(wb + WG_OFF, fh, D, rowin, mq);

        // ---- y, LN, weighted select ----
        float sum0 = 0.f, sq0 = 0.f, sum1 = 0.f, sq1 = 0.f;
#pragma unroll
        for (int j = 0; j < 8; j++) {
            int o = 4 * (j >> 1) + 2 * (j & 1);
            u32 h0 = fh[o], h1r = fh[o + 1];
            float h2a = flo(h0), h2b = fhi(h0);
            float h2c = flo(h1r), h2d = fhi(h1r);
            float y0 = fmaf(sigm(D[4*j+0]), h2a, Dres[4*j+0]);
            float y1 = fmaf(sigm(D[4*j+1]), h2b, Dres[4*j+1]);
            float y2 = fmaf(sigm(D[4*j+2]), h2c, Dres[4*j+2]);
            float y3 = fmaf(sigm(D[4*j+3]), h2d, Dres[4*j+3]);
            D[4*j+0] = y0; D[4*j+1] = y1; D[4*j+2] = y2; D[4*j+3] = y3;
            sum0 += y0 + y1; sq0 = fmaf(y0, y0, fmaf(y1, y1, sq0));
            sum1 += y2 + y3; sq1 = fmaf(y2, y2, fmaf(y3, y3, sq1));
        }
        sum0 += __shfl_xor_sync(0xffffffffu, sum0, 1);
        sum0 += __shfl_xor_sync(0xffffffffu, sum0, 2);
        sq0  += __shfl_xor_sync(0xffffffffu, sq0, 1);
        sq0  += __shfl_xor_sync(0xffffffffu, sq0, 2);
        sum1 += __shfl_xor_sync(0xffffffffu, sum1, 1);
        sum1 += __shfl_xor_sync(0xffffffffu, sum1, 2);
        sq1  += __shfl_xor_sync(0xffffffffu, sq1, 1);
        sq1  += __shfl_xor_sync(0xffffffffu, sq1, 2);
        float mu0 = sum0 * (1.f / 64.f);
        float rs0 = rsqrtf(sq0 * (1.f / 64.f) - mu0 * mu0 + LN_EPS);
        float mu1 = sum1 * (1.f / 64.f);
        float rs1 = rsqrtf(sq1 * (1.f / 64.f) - mu1 * mu1 + LN_EPS);
        float w0 = wsel_s[row0 * NVARS + n];
        float w1 = wsel_s[row1 * NVARS + n];
#pragma unroll
        for (int j = 0; j < 8; j++) {
            float2 gm = *(const float2*)(bv + 5 * DD + 8 * j + 2 * tig);
            float2 be = *(const float2*)(bv + 6 * DD + 8 * j + 2 * tig);
            float yn0 = fmaf((D[4*j+0] - mu0) * rs0, gm.x, be.x);
            float yn1 = fmaf((D[4*j+1] - mu0) * rs0, gm.y, be.y);
            float yn2 = fmaf((D[4*j+2] - mu1) * rs1, gm.x, be.x);
            float yn3 = fmaf((D[4*j+3] - mu1) * rs1, gm.y, be.y);
            sel[4*j+0] = fmaf(w0, yn0, sel[4*j+0]);
            sel[4*j+1] = fmaf(w0, yn1, sel[4*j+1]);
            sel[4*j+2] = fmaf(w1, yn2, sel[4*j+2]);
            sel[4*j+3] = fmaf(w1, yn3, sel[4*j+3]);
        }
        __syncthreads();
    }

    // ---- output ----
#pragma unroll
    for (int j = 0; j < 8; j++) {
        *(float2*)(selected + (size_t)tok0 * DD + 8 * j + 2 * tig)
            = make_float2(sel[4*j+0], sel[4*j+1]);
        *(float2*)(selected + (size_t)tok1 * DD + 8 * j + 2 * tig)
            = make_float2(sel[4*j+2], sel[4*j+3]);
    }
}

// ---------------------------------------------------------------------------
extern "C" void kernel_launch(void* const* d_in, const int* in_sizes, int n_in,
                              void* d_out, int out_size) {
    const float* inputs  = (const float*)d_in[0];
    const float* context = (const float*)d_in[1];
    const float* Wt   = (const float*)d_in[2];
    const float* bt   = (const float*)d_in[3];
    const float* Wctx = (const float*)d_in[4];
    const float* W1   = (const float*)d_in[5];
    const float* b1   = (const float*)d_in[6];
    const float* W2   = (const float*)d_in[7];
    const float* b2   = (const float*)d_in[8];
    const float* Wg   = (const float*)d_in[9];
    const float* bg   = (const float*)d_in[10];
    const float* Wp   = (const float*)d_in[11];
    const float* bp   = (const float*)d_in[12];
    const float* gam  = (const float*)d_in[13];
    const float* bet  = (const float*)d_in[14];
    const float* Ws   = (const float*)d_in[15];
    const float* bs   = (const float*)d_in[16];

    float* selected = (float*)d_out;
    float* wout = selected + (size_t)NTOK * DD;

    prep_weights_kernel<<<dim3(NVARS, 5), 256>>>(Wt, Wp, W1, W2, Wg);

    cudaFuncSetAttribute(vsn_mma_kernel,
                         cudaFuncAttributeMaxDynamicSharedMemorySize, SMEM_TOTAL);
    vsn_mma_kernel<<<NTOK / MTILE, TPB, SMEM_TOTAL>>>(
        inputs, context, Wctx, Wp, bt, b1, b2, bg, bp, gam, bet, Ws, bs,
        wout, selected);
}